// round 4
// baseline (speedup 1.0000x reference)
#include <cuda_runtime.h>
#include <cuda_bf16.h>

// Problem constants
#define Bx    16
#define Sx    1024
#define Dx    768
#define NSx   256
#define MAXWx 8
#define Vx    128
#define Cx    6
#define Rx    512
#define RELx  97
#define HIDx  384
#define DISx  20
#define FINx  (Dx + DISx)          // 788
#define KF    (2 * FINx + Dx)      // 2344
#define MROWS (Bx * Rx)            // 8192

// Scratch (static device globals — no allocation allowed)
__device__ float g_span[(size_t)Bx * NSx * Dx];      // 12.6 MB
__device__ float g_vert[(size_t)Bx * Vx * Dx];       //  6.3 MB
__device__ float g_feat[(size_t)MROWS * KF];         // 76.8 MB
__device__ float g_hid[(size_t)MROWS * HIDx];        // 12.6 MB

// ---------------------------------------------------------------------------
// Stage 1: span max-pool.  grid = B*NS blocks, 192 threads (float4 over D=768)
// ---------------------------------------------------------------------------
__global__ void span_kernel(const float* __restrict__ sent,
                            const int* __restrict__ spans) {
    int bs = blockIdx.x;              // b*NS + ns
    int b  = bs / NSx;
    int start = spans[bs * 2 + 0];
    int end   = spans[bs * 2 + 1];    // start + width, width in [0,7]
    int w = end - start;
    const float4* base =
        (const float4*)(sent + ((size_t)b * Sx + start) * Dx);
    int t = threadIdx.x;              // 0..191
    float4 m = base[t];
    for (int j = 1; j <= w; j++) {
        float4 v = base[(size_t)j * (Dx / 4) + t];
        m.x = fmaxf(m.x, v.x);
        m.y = fmaxf(m.y, v.y);
        m.z = fmaxf(m.z, v.z);
        m.w = fmaxf(m.w, v.w);
    }
    ((float4*)(g_span + (size_t)bs * Dx))[t] = m;
}

// ---------------------------------------------------------------------------
// Stage 2: vertex masked mean.  grid = B*V blocks, 192 threads
// ---------------------------------------------------------------------------
__global__ void vertex_kernel(const int* __restrict__ vidx,
                              const int* __restrict__ vmask) {
    int bv = blockIdx.x;              // b*V + v
    int b  = bv / Vx;
    int t  = threadIdx.x;
    float4 acc = make_float4(0.f, 0.f, 0.f, 0.f);
    float cnt = 0.f;
    #pragma unroll
    for (int c = 0; c < Cx; c++) {
        int mk = vmask[bv * Cx + c];
        if (mk) {
            int idx = vidx[bv * Cx + c];
            const float4* sp =
                (const float4*)(g_span + ((size_t)b * NSx + idx) * Dx);
            float4 v = sp[t];
            acc.x += v.x; acc.y += v.y; acc.z += v.z; acc.w += v.w;
            cnt += 1.f;
        }
    }
    float inv = 1.f / fmaxf(cnt, 1.f);
    acc.x *= inv; acc.y *= inv; acc.z *= inv; acc.w *= inv;
    ((float4*)(g_vert + (size_t)bv * Dx))[t] = acc;
}

// ---------------------------------------------------------------------------
// Stage 3: feature assembly.  grid = 8192 rows, 256 threads
// feat row = [head(768) | eh(20) | tail(768) | et(20) | head*tail(768)]
// ---------------------------------------------------------------------------
__global__ void feat_kernel(const int* __restrict__ hti,
                            const int* __restrict__ dht,
                            const int* __restrict__ dth,
                            const float* __restrict__ dis) {
    int m = blockIdx.x;
    int b = m / Rx;
    int h  = hti[m * 2 + 0];
    int tl = hti[m * 2 + 1];
    const float* hp = g_vert + ((size_t)b * Vx + h)  * Dx;
    const float* tp = g_vert + ((size_t)b * Vx + tl) * Dx;
    const float* eh = dis + (size_t)dht[m] * DISx;
    const float* et = dis + (size_t)dth[m] * DISx;
    float* out = g_feat + (size_t)m * KF;
    for (int k = threadIdx.x; k < KF; k += blockDim.x) {
        float v;
        if (k < Dx)                 v = hp[k];
        else if (k < FINx)          v = eh[k - Dx];
        else if (k < FINx + Dx)     v = tp[k - FINx];
        else if (k < 2 * FINx)      v = et[k - FINx - Dx];
        else { int q = k - 2 * FINx; v = hp[q] * tp[q]; }
        out[k] = v;
    }
}

// ---------------------------------------------------------------------------
// Stage 4: GEMM1  (8192 x 2344) @ (2344 x 384) + ReLU -> g_hid
// BM=128, BN=64, BK=8; 256 threads; per-thread 8x4. All dims divide evenly.
// ---------------------------------------------------------------------------
#define G1_BM 128
#define G1_BN 64
#define G1_BK 8

__global__ __launch_bounds__(256) void gemm1_kernel(const float* __restrict__ W1) {
    __shared__ float As[G1_BK][132];   // [k][m], stride 132 -> conflict-free STS
    __shared__ float Bs[G1_BK][G1_BN];

    int m0 = blockIdx.x * G1_BM;
    int n0 = blockIdx.y * G1_BN;
    int t  = threadIdx.x;
    int tx = t & 15;       // col group (TN=4)
    int ty = t >> 4;       // row group (TM=8)

    float acc[8][4];
    #pragma unroll
    for (int i = 0; i < 8; i++)
        #pragma unroll
        for (int j = 0; j < 4; j++) acc[i][j] = 0.f;

    int arow = t >> 1;           // 0..127
    int ac   = (t & 1) * 4;      // 0 or 4
    const float* Aptr = g_feat + (size_t)(m0 + arow) * KF + ac;
    int bk = t >> 4;             // for B loads (t<128): k row
    int bc = (t & 15) * 4;       // col

    for (int k0 = 0; k0 < KF; k0 += G1_BK) {
        float4 av = *(const float4*)(Aptr + k0);
        As[ac + 0][arow] = av.x;
        As[ac + 1][arow] = av.y;
        As[ac + 2][arow] = av.z;
        As[ac + 3][arow] = av.w;
        if (t < 128) {
            float4 bv = *(const float4*)(W1 + (size_t)(k0 + bk) * HIDx + n0 + bc);
            *(float4*)&Bs[bk][bc] = bv;
        }
        __syncthreads();
        #pragma unroll
        for (int kk = 0; kk < G1_BK; kk++) {
            float4 a0 = *(float4*)&As[kk][ty * 8];
            float4 a1 = *(float4*)&As[kk][ty * 8 + 4];
            float4 b0 = *(float4*)&Bs[kk][tx * 4];
            float a[8] = {a0.x, a0.y, a0.z, a0.w, a1.x, a1.y, a1.z, a1.w};
            float bb[4] = {b0.x, b0.y, b0.z, b0.w};
            #pragma unroll
            for (int i = 0; i < 8; i++)
                #pragma unroll
                for (int j = 0; j < 4; j++)
                    acc[i][j] += a[i] * bb[j];
        }
        __syncthreads();
    }

    #pragma unroll
    for (int i = 0; i < 8; i++) {
        float4 o;
        o.x = fmaxf(acc[i][0], 0.f);
        o.y = fmaxf(acc[i][1], 0.f);
        o.z = fmaxf(acc[i][2], 0.f);
        o.w = fmaxf(acc[i][3], 0.f);
        *(float4*)(g_hid + (size_t)(m0 + ty * 8 + i) * HIDx + n0 + tx * 4) = o;
    }
}

// ---------------------------------------------------------------------------
// Stage 5: GEMM2  relu'd hid (8192 x 384) @ W2 (384 x 97) + b2 -> out
// Same tiling, guarded on N (97).  W2 ld=97 -> scalar loads.
// ---------------------------------------------------------------------------
#define G2_BM 128
#define G2_BN 64
#define G2_BK 8

__global__ __launch_bounds__(256) void gemm2_kernel(const float* __restrict__ W2,
                                                    const float* __restrict__ bias,
                                                    float* __restrict__ out) {
    __shared__ float As[G2_BK][132];
    __shared__ float Bs[G2_BK][G2_BN];

    int m0 = blockIdx.x * G2_BM;
    int n0 = blockIdx.y * G2_BN;
    int t  = threadIdx.x;
    int tx = t & 15;
    int ty = t >> 4;

    float acc[8][4];
    #pragma unroll
    for (int i = 0; i < 8; i++)
        #pragma unroll
        for (int j = 0; j < 4; j++) acc[i][j] = 0.f;

    int arow = t >> 1;
    int ac   = (t & 1) * 4;
    const float* Aptr = g_hid + (size_t)(m0 + arow) * HIDx + ac;

    for (int k0 = 0; k0 < HIDx; k0 += G2_BK) {
        float4 av = *(const float4*)(Aptr + k0);
        As[ac + 0][arow] = av.x;
        As[ac + 1][arow] = av.y;
        As[ac + 2][arow] = av.z;
        As[ac + 3][arow] = av.w;
        #pragma unroll
        for (int e = t; e < G2_BK * G2_BN; e += 256) {
            int kk = e >> 6, cc = e & 63;
            int n = n0 + cc;
            Bs[kk][cc] = (n < RELx) ? W2[(size_t)(k0 + kk) * RELx + n] : 0.f;
        }
        __syncthreads();
        #pragma unroll
        for (int kk = 0; kk < G2_BK; kk++) {
            float4 a0 = *(float4*)&As[kk][ty * 8];
            float4 a1 = *(float4*)&As[kk][ty * 8 + 4];
            float4 b0 = *(float4*)&Bs[kk][tx * 4];
            float a[8] = {a0.x, a0.y, a0.z, a0.w, a1.x, a1.y, a1.z, a1.w};
            float bb[4] = {b0.x, b0.y, b0.z, b0.w};
            #pragma unroll
            for (int i = 0; i < 8; i++)
                #pragma unroll
                for (int j = 0; j < 4; j++)
                    acc[i][j] += a[i] * bb[j];
        }
        __syncthreads();
    }

    #pragma unroll
    for (int i = 0; i < 8; i++) {
        int mm = m0 + ty * 8 + i;
        #pragma unroll
        for (int j = 0; j < 4; j++) {
            int n = n0 + tx * 4 + j;
            if (n < RELx)
                out[(size_t)mm * RELx + n] = acc[i][j] + bias[n];
        }
    }
}

// ---------------------------------------------------------------------------
// Launch.  Input order per metadata:
// 0 sentence_repr f32, 1 entity_span_indices i32, 2 entity_span_indices_mask,
// 3 vertex_indices, 4 vertex_indices_mask, 5 head_tail_indices,
// 6 relation_mask, 7 dis_h_2_t, 8 dis_t_2_h, 9 dis_embed f32,
// 10 W1 f32, 11 W2 f32, 12 b2 f32.   (2 and 6 are unused by the reference.)
// ---------------------------------------------------------------------------
extern "C" void kernel_launch(void* const* d_in, const int* in_sizes, int n_in,
                              void* d_out, int out_size) {
    const float* sent  = (const float*)d_in[0];
    const int*   spans = (const int*)d_in[1];
    const int*   vidx  = (const int*)d_in[3];
    const int*   vmask = (const int*)d_in[4];
    const int*   hti   = (const int*)d_in[5];
    const int*   dht   = (const int*)d_in[7];
    const int*   dth   = (const int*)d_in[8];
    const float* dis   = (const float*)d_in[9];
    const float* W1    = (const float*)d_in[10];
    const float* W2    = (const float*)d_in[11];
    const float* b2    = (const float*)d_in[12];
    float* out = (float*)d_out;

    span_kernel<<<Bx * NSx, 192>>>(sent, spans);
    vertex_kernel<<<Bx * Vx, 192>>>(vidx, vmask);
    feat_kernel<<<MROWS, 256>>>(hti, dht, dth, dis);
    gemm1_kernel<<<dim3(MROWS / G1_BM, HIDx / G1_BN), 256>>>(W1);
    gemm2_kernel<<<dim3(MROWS / G2_BM, (RELx + G2_BN - 1) / G2_BN), 256>>>(W2, b2, out);
}

// round 7
// speedup vs baseline: 1.5310x; 1.5310x over previous
#include <cuda_runtime.h>
#include <cuda_bf16.h>
#include <cstdint>

// Problem constants
#define Bx    16
#define Sx    1024
#define Dx    768
#define NSx   256
#define MAXWx 8
#define Vx    128
#define Cx    6
#define Rx    512
#define RELx  97
#define HIDx  384
#define DISx  20
#define FINx  (Dx + DISx)          // 788
#define KF    (2 * FINx + Dx)      // 2344
#define KP    2368                 // padded: 74 * 32
#define MROWS (Bx * Rx)            // 8192
#define BKx   32
#define NCHUNK (KP / BKx)          // 74

// Scratch (static device globals — no allocation allowed)
__device__ float g_span[(size_t)Bx * NSx * Dx];
__device__ float g_vert[(size_t)Bx * Vx * Dx];
__device__ __align__(16) __nv_bfloat16 g_ahi[(size_t)MROWS * KP];
__device__ __align__(16) __nv_bfloat16 g_alo[(size_t)MROWS * KP];
__device__ __align__(16) __nv_bfloat16 g_bhi[(size_t)HIDx * KP];   // W1^T hi
__device__ __align__(16) __nv_bfloat16 g_blo[(size_t)HIDx * KP];   // W1^T lo
__device__ float g_hid[(size_t)MROWS * HIDx];

// ---------------------------------------------------------------------------
// PTX helpers (sm_80-era only: ldmatrix / mma.sync / cp.async — all of these
// assemble for the harness's compute_103 PTX target; tcgen05 does NOT)
// ---------------------------------------------------------------------------
__device__ __forceinline__ uint32_t smem_u32(const void* p) {
    uint32_t a;
    asm("{ .reg .u64 t; cvta.to.shared.u64 t, %1; cvt.u32.u64 %0, t; }"
        : "=r"(a) : "l"(p));
    return a;
}

__device__ __forceinline__ void ldsm4(uint32_t* r, uint32_t addr) {
    asm volatile("ldmatrix.sync.aligned.m8n8.x4.shared.b16 {%0,%1,%2,%3}, [%4];"
                 : "=r"(r[0]), "=r"(r[1]), "=r"(r[2]), "=r"(r[3]) : "r"(addr));
}

__device__ __forceinline__ void mma_bf16(float* d, const uint32_t* a,
                                         uint32_t b0, uint32_t b1) {
    asm volatile(
        "mma.sync.aligned.m16n8k16.row.col.f32.bf16.bf16.f32 "
        "{%0,%1,%2,%3}, {%4,%5,%6,%7}, {%8,%9}, {%0,%1,%2,%3};"
        : "+f"(d[0]), "+f"(d[1]), "+f"(d[2]), "+f"(d[3])
        : "r"(a[0]), "r"(a[1]), "r"(a[2]), "r"(a[3]), "r"(b0), "r"(b1));
}

__device__ __forceinline__ void cp16(uint32_t dst, const void* src) {
    asm volatile("cp.async.cg.shared.global [%0], [%1], 16;"
                 :: "r"(dst), "l"(src));
}
#define CP_COMMIT() asm volatile("cp.async.commit_group;" ::: "memory")
#define CP_WAIT(n)  asm volatile("cp.async.wait_group %0;" :: "n"(n) : "memory")

// ---------------------------------------------------------------------------
// Stage 1: span max-pool
// ---------------------------------------------------------------------------
__global__ void span_kernel(const float* __restrict__ sent,
                            const int* __restrict__ spans) {
    int bs = blockIdx.x;
    int b  = bs / NSx;
    int start = spans[bs * 2 + 0];
    int end   = spans[bs * 2 + 1];
    int w = end - start;
    const float4* base = (const float4*)(sent + ((size_t)b * Sx + start) * Dx);
    int t = threadIdx.x;
    float4 m = base[t];
    for (int j = 1; j <= w; j++) {
        float4 v = base[(size_t)j * (Dx / 4) + t];
        m.x = fmaxf(m.x, v.x); m.y = fmaxf(m.y, v.y);
        m.z = fmaxf(m.z, v.z); m.w = fmaxf(m.w, v.w);
    }
    ((float4*)(g_span + (size_t)bs * Dx))[t] = m;
}

// ---------------------------------------------------------------------------
// Stage 2: vertex masked mean
// ---------------------------------------------------------------------------
__global__ void vertex_kernel(const int* __restrict__ vidx,
                              const int* __restrict__ vmask) {
    int bv = blockIdx.x;
    int b  = bv / Vx;
    int t  = threadIdx.x;
    float4 acc = make_float4(0.f, 0.f, 0.f, 0.f);
    float cnt = 0.f;
    #pragma unroll
    for (int c = 0; c < Cx; c++) {
        int mk = vmask[bv * Cx + c];
        if (mk) {
            int idx = vidx[bv * Cx + c];
            float4 v = ((const float4*)(g_span + ((size_t)b * NSx + idx) * Dx))[t];
            acc.x += v.x; acc.y += v.y; acc.z += v.z; acc.w += v.w;
            cnt += 1.f;
        }
    }
    float inv = 1.f / fmaxf(cnt, 1.f);
    acc.x *= inv; acc.y *= inv; acc.z *= inv; acc.w *= inv;
    ((float4*)(g_vert + (size_t)bv * Dx))[t] = acc;
}

// ---------------------------------------------------------------------------
// Stage 3: feature assembly -> bf16 hi/lo split, K padded to 2368
// ---------------------------------------------------------------------------
__global__ void feat_kernel(const int* __restrict__ hti,
                            const int* __restrict__ dht,
                            const int* __restrict__ dth,
                            const float* __restrict__ dis) {
    int m = blockIdx.x;
    int b = m / Rx;
    int h  = hti[m * 2 + 0];
    int tl = hti[m * 2 + 1];
    const float* hp = g_vert + ((size_t)b * Vx + h)  * Dx;
    const float* tp = g_vert + ((size_t)b * Vx + tl) * Dx;
    const float* eh = dis + (size_t)dht[m] * DISx;
    const float* et = dis + (size_t)dth[m] * DISx;
    size_t rowoff = (size_t)m * KP;
    for (int k = threadIdx.x; k < KP; k += blockDim.x) {
        float v = 0.f;
        if (k < Dx)                 v = hp[k];
        else if (k < FINx)          v = eh[k - Dx];
        else if (k < FINx + Dx)     v = tp[k - FINx];
        else if (k < 2 * FINx)      v = et[k - FINx - Dx];
        else if (k < KF) { int q = k - 2 * FINx; v = hp[q] * tp[q]; }
        __nv_bfloat16 hi = __float2bfloat16(v);
        float lo = v - __bfloat162float(hi);
        g_ahi[rowoff + k] = hi;
        g_alo[rowoff + k] = __float2bfloat16(lo);
    }
}

// ---------------------------------------------------------------------------
// Stage 3b: W1 transpose + hi/lo split.  W1[K x 384] -> Bt[384 x KP]
// ---------------------------------------------------------------------------
__global__ void prep_w1(const float* __restrict__ W1) {
    int n = blockIdx.x;                       // 0..383
    size_t rowoff = (size_t)n * KP;
    for (int k = threadIdx.x; k < KP; k += blockDim.x) {
        float v = (k < KF) ? W1[(size_t)k * HIDx + n] : 0.f;
        __nv_bfloat16 hi = __float2bfloat16(v);
        float lo = v - __bfloat162float(hi);
        g_bhi[rowoff + k] = hi;
        g_blo[rowoff + k] = __float2bfloat16(lo);
    }
}

// ---------------------------------------------------------------------------
// Stage 4: GEMM1 via mma.sync (HMMA bf16, fp32 accum), hi/lo 3-stream.
//   D[8192x384] = A[8192xKP] * Bt^T.
//   BM=128, BN=128, BK=32; 8 warps, warp tile 64x32 (4 m-frags x 4 n-frags).
//   cp.async double-buffered SMEM; rows padded to 40 bf16 (80B) ->
//   conflict-free ldmatrix (80B stride: 16B-group pattern 0,5,2,7,4,1,6,3).
// ---------------------------------------------------------------------------
#define PAD    40                       // bf16 elems per smem row
#define ARR_B  (128 * PAD * 2)          // 10240 B per array (Ahi/Alo/Bhi/Blo)
#define STG_B  (4 * ARR_B)              // 40960 B per stage
#define G1_SMEM (2 * STG_B)             // 81920 B

__global__ __launch_bounds__(256, 1) void gemm1_mma() {
    extern __shared__ char smem[];
    uint32_t sb = smem_u32(smem);
    int t = threadIdx.x, wid = t >> 5, lane = t & 31;
    int m0 = blockIdx.x * 128;
    int n0 = blockIdx.y * 128;
    int wm = (wid >> 2) * 64;           // warp m offset (0 / 64)
    int wn = (wid & 3) * 32;            // warp n offset (0/32/64/96)

    float acc[4][4][4];
    #pragma unroll
    for (int i = 0; i < 4; i++)
        #pragma unroll
        for (int j = 0; j < 4; j++)
            #pragma unroll
            for (int q = 0; q < 4; q++) acc[i][j][q] = 0.f;

    // --- async tile loader: 2048 x 16B chunks, 8 per thread ---
    auto load_chunk = [&](int k0, int s) {
        uint32_t stg = sb + (uint32_t)s * STG_B;
        #pragma unroll
        for (int i = 0; i < 8; i++) {
            int arr = i >> 1;                       // 0..3
            int w   = ((i & 1) << 8) + t;           // 0..511
            int r   = w >> 2;                       // row 0..127
            int c   = w & 3;                        // 16B chunk in row
            const __nv_bfloat16* base =
                (arr == 0) ? g_ahi : (arr == 1) ? g_alo :
                (arr == 2) ? g_bhi : g_blo;
            int rb = (arr < 2) ? m0 : n0;
            const __nv_bfloat16* src = base + (size_t)(rb + r) * KP + k0 + c * 8;
            uint32_t dst = stg + (uint32_t)arr * ARR_B + r * (PAD * 2) + c * 16;
            cp16(dst, src);
        }
    };

    load_chunk(0, 0);
    CP_COMMIT();

    int lr = lane & 15;                 // ldmatrix row-within-frag
    int lc = lane >> 4;                 // ldmatrix 8-col group

    for (int c = 0; c < NCHUNK; c++) {
        int s = c & 1;
        if (c + 1 < NCHUNK) {
            load_chunk((c + 1) * BKx, s ^ 1);
            CP_COMMIT();
            CP_WAIT(1);
        } else {
            CP_WAIT(0);
        }
        __syncthreads();

        uint32_t a_base = sb + (uint32_t)s * STG_B;
        uint32_t b_base = a_base + 2 * ARR_B;

        #pragma unroll
        for (int ks = 0; ks < 2; ks++) {
            uint32_t koff = (uint32_t)(ks * 16 + lc * 8) * 2;
            uint32_t ahi[4][4], alo[4][4];
            #pragma unroll
            for (int mf = 0; mf < 4; mf++) {
                uint32_t ro = (uint32_t)(wm + mf * 16 + lr) * (PAD * 2) + koff;
                ldsm4(ahi[mf], a_base + ro);
                ldsm4(alo[mf], a_base + ARR_B + ro);
            }
            uint32_t bhi[8], blo[8];
            #pragma unroll
            for (int g = 0; g < 2; g++) {
                uint32_t ro = (uint32_t)(wn + g * 16 + lr) * (PAD * 2) + koff;
                ldsm4(&bhi[g * 4], b_base + ro);
                ldsm4(&blo[g * 4], b_base + ARR_B + ro);
            }
            // x4 of [n16][k16] -> r0=(n0-7,k0-7) r1=(n8-15,k0-7)
            //                    r2=(n0-7,k8-15) r3=(n8-15,k8-15)
            // frag nf: b0 = [(nf>>1)*4 + (nf&1)], b1 = same + 2
            #pragma unroll
            for (int mf = 0; mf < 4; mf++) {
                #pragma unroll
                for (int nf = 0; nf < 4; nf++) {
                    int bi = (nf >> 1) * 4 + (nf & 1);
                    mma_bf16(acc[mf][nf], ahi[mf], bhi[bi], bhi[bi + 2]);
                    mma_bf16(acc[mf][nf], ahi[mf], blo[bi], blo[bi + 2]);
                    mma_bf16(acc[mf][nf], alo[mf], bhi[bi], bhi[bi + 2]);
                }
            }
        }
        __syncthreads();
    }

    // Epilogue: ReLU, write g_hid (fp32)
    int row  = lane >> 2;
    int colp = (lane & 3) * 2;
    #pragma unroll
    for (int mf = 0; mf < 4; mf++) {
        #pragma unroll
        for (int nf = 0; nf < 4; nf++) {
            int r0 = m0 + wm + mf * 16 + row;
            int cc = n0 + wn + nf * 8 + colp;
            float2 v0, v1;
            v0.x = fmaxf(acc[mf][nf][0], 0.f);
            v0.y = fmaxf(acc[mf][nf][1], 0.f);
            v1.x = fmaxf(acc[mf][nf][2], 0.f);
            v1.y = fmaxf(acc[mf][nf][3], 0.f);
            *(float2*)(g_hid + (size_t)r0 * HIDx + cc)       = v0;
            *(float2*)(g_hid + (size_t)(r0 + 8) * HIDx + cc) = v1;
        }
    }
}

// ---------------------------------------------------------------------------
// Stage 5: GEMM2  hid (8192 x 384) @ W2 (384 x 97) + b2 -> out  (SIMT fp32)
// ---------------------------------------------------------------------------
#define G2_BM 128
#define G2_BN 64
#define G2_BK 8

__global__ __launch_bounds__(256) void gemm2_kernel(const float* __restrict__ W2,
                                                    const float* __restrict__ bias,
                                                    float* __restrict__ out) {
    __shared__ float As[G2_BK][132];
    __shared__ float Bs[G2_BK][G2_BN];

    int m0 = blockIdx.x * G2_BM;
    int n0 = blockIdx.y * G2_BN;
    int t  = threadIdx.x;
    int tx = t & 15;
    int ty = t >> 4;

    float acc[8][4];
    #pragma unroll
    for (int i = 0; i < 8; i++)
        #pragma unroll
        for (int j = 0; j < 4; j++) acc[i][j] = 0.f;

    int arow = t >> 1;
    int ac   = (t & 1) * 4;
    const float* Aptr = g_hid + (size_t)(m0 + arow) * HIDx + ac;

    for (int k0 = 0; k0 < HIDx; k0 += G2_BK) {
        float4 av = *(const float4*)(Aptr + k0);
        As[ac + 0][arow] = av.x;
        As[ac + 1][arow] = av.y;
        As[ac + 2][arow] = av.z;
        As[ac + 3][arow] = av.w;
        #pragma unroll
        for (int e = t; e < G2_BK * G2_BN; e += 256) {
            int kk = e >> 6, cc = e & 63;
            int n = n0 + cc;
            Bs[kk][cc] = (n < RELx) ? W2[(size_t)(k0 + kk) * RELx + n] : 0.f;
        }
        __syncthreads();
        #pragma unroll
        for (int kk = 0; kk < G2_BK; kk++) {
            float4 a0 = *(float4*)&As[kk][ty * 8];
            float4 a1 = *(float4*)&As[kk][ty * 8 + 4];
            float4 b0 = *(float4*)&Bs[kk][tx * 4];
            float a[8] = {a0.x, a0.y, a0.z, a0.w, a1.x, a1.y, a1.z, a1.w};
            float bb[4] = {b0.x, b0.y, b0.z, b0.w};
            #pragma unroll
            for (int i = 0; i < 8; i++)
                #pragma unroll
                for (int j = 0; j < 4; j++)
                    acc[i][j] += a[i] * bb[j];
        }
        __syncthreads();
    }

    #pragma unroll
    for (int i = 0; i < 8; i++) {
        int mm = m0 + ty * 8 + i;
        #pragma unroll
        for (int j = 0; j < 4; j++) {
            int n = n0 + tx * 4 + j;
            if (n < RELx)
                out[(size_t)mm * RELx + n] = acc[i][j] + bias[n];
        }
    }
}

// ---------------------------------------------------------------------------
// Launch
// ---------------------------------------------------------------------------
extern "C" void kernel_launch(void* const* d_in, const int* in_sizes, int n_in,
                              void* d_out, int out_size) {
    const float* sent  = (const float*)d_in[0];
    const int*   spans = (const int*)d_in[1];
    const int*   vidx  = (const int*)d_in[3];
    const int*   vmask = (const int*)d_in[4];
    const int*   hti   = (const int*)d_in[5];
    const int*   dht   = (const int*)d_in[7];
    const int*   dth   = (const int*)d_in[8];
    const float* dis   = (const float*)d_in[9];
    const float* W1    = (const float*)d_in[10];
    const float* W2    = (const float*)d_in[11];
    const float* b2    = (const float*)d_in[12];
    float* out = (float*)d_out;

    cudaFuncSetAttribute(gemm1_mma, cudaFuncAttributeMaxDynamicSharedMemorySize,
                         G1_SMEM);

    span_kernel<<<Bx * NSx, 192>>>(sent, spans);
    vertex_kernel<<<Bx * Vx, 192>>>(vidx, vmask);
    feat_kernel<<<MROWS, 256>>>(hti, dht, dth, dis);
    prep_w1<<<HIDx, 256>>>(W1);
    gemm1_mma<<<dim3(MROWS / 128, HIDx / 128), 256, G1_SMEM>>>();
    gemm2_kernel<<<dim3(MROWS / G2_BM, (RELx + G2_BN - 1) / G2_BN), 256>>>(W2, b2, out);
}

// round 8
// speedup vs baseline: 1.7154x; 1.1205x over previous
#include <cuda_runtime.h>
#include <cuda_bf16.h>
#include <cstdint>

// Problem constants
#define Bx    16
#define Sx    1024
#define Dx    768
#define NSx   256
#define MAXWx 8
#define Vx    128
#define Cx    6
#define Rx    512
#define RELx  97
#define HIDx  384
#define DISx  20
#define FINx  (Dx + DISx)          // 788
#define KF    (2 * FINx + Dx)      // 2344
#define KP    2368                 // padded: 74 * 32
#define MROWS (Bx * Rx)            // 8192
#define BKx   32
#define NCHUNK (KP / BKx)          // 74

// Scratch (static device globals — no allocation allowed)
__device__ float g_span[(size_t)Bx * NSx * Dx];
__device__ float g_vert[(size_t)Bx * Vx * Dx];
__device__ __align__(16) __nv_bfloat16 g_ahi[(size_t)MROWS * KP];
__device__ __align__(16) __nv_bfloat16 g_alo[(size_t)MROWS * KP];
__device__ __align__(16) __nv_bfloat16 g_bhi[(size_t)HIDx * KP];   // W1^T hi
__device__ __align__(16) __nv_bfloat16 g_blo[(size_t)HIDx * KP];   // W1^T lo
__device__ float g_hid[(size_t)MROWS * HIDx];

// ---------------------------------------------------------------------------
// PTX helpers (sm_80-era only: ldmatrix / mma.sync / cp.async — these
// assemble for the harness's compute_103 PTX target; tcgen05 does NOT)
// ---------------------------------------------------------------------------
__device__ __forceinline__ uint32_t smem_u32(const void* p) {
    uint32_t a;
    asm("{ .reg .u64 t; cvta.to.shared.u64 t, %1; cvt.u32.u64 %0, t; }"
        : "=r"(a) : "l"(p));
    return a;
}

__device__ __forceinline__ void ldsm4(uint32_t* r, uint32_t addr) {
    asm volatile("ldmatrix.sync.aligned.m8n8.x4.shared.b16 {%0,%1,%2,%3}, [%4];"
                 : "=r"(r[0]), "=r"(r[1]), "=r"(r[2]), "=r"(r[3]) : "r"(addr));
}

__device__ __forceinline__ void mma_bf16(float* d, const uint32_t* a,
                                         uint32_t b0, uint32_t b1) {
    asm volatile(
        "mma.sync.aligned.m16n8k16.row.col.f32.bf16.bf16.f32 "
        "{%0,%1,%2,%3}, {%4,%5,%6,%7}, {%8,%9}, {%0,%1,%2,%3};"
        : "+f"(d[0]), "+f"(d[1]), "+f"(d[2]), "+f"(d[3])
        : "r"(a[0]), "r"(a[1]), "r"(a[2]), "r"(a[3]), "r"(b0), "r"(b1));
}

__device__ __forceinline__ void cp16(uint32_t dst, const void* src) {
    asm volatile("cp.async.cg.shared.global [%0], [%1], 16;"
                 :: "r"(dst), "l"(src));
}
#define CP_COMMIT() asm volatile("cp.async.commit_group;" ::: "memory")
#define CP_WAIT(n)  asm volatile("cp.async.wait_group %0;" :: "n"(n) : "memory")

// ---------------------------------------------------------------------------
// Stage 1: span max-pool
// ---------------------------------------------------------------------------
__global__ void span_kernel(const float* __restrict__ sent,
                            const int* __restrict__ spans) {
    int bs = blockIdx.x;
    int b  = bs / NSx;
    int start = spans[bs * 2 + 0];
    int end   = spans[bs * 2 + 1];
    int w = end - start;
    const float4* base = (const float4*)(sent + ((size_t)b * Sx + start) * Dx);
    int t = threadIdx.x;
    float4 m = base[t];
    for (int j = 1; j <= w; j++) {
        float4 v = base[(size_t)j * (Dx / 4) + t];
        m.x = fmaxf(m.x, v.x); m.y = fmaxf(m.y, v.y);
        m.z = fmaxf(m.z, v.z); m.w = fmaxf(m.w, v.w);
    }
    ((float4*)(g_span + (size_t)bs * Dx))[t] = m;
}

// ---------------------------------------------------------------------------
// Stage 2: vertex masked mean
// ---------------------------------------------------------------------------
__global__ void vertex_kernel(const int* __restrict__ vidx,
                              const int* __restrict__ vmask) {
    int bv = blockIdx.x;
    int b  = bv / Vx;
    int t  = threadIdx.x;
    float4 acc = make_float4(0.f, 0.f, 0.f, 0.f);
    float cnt = 0.f;
    #pragma unroll
    for (int c = 0; c < Cx; c++) {
        int mk = vmask[bv * Cx + c];
        if (mk) {
            int idx = vidx[bv * Cx + c];
            float4 v = ((const float4*)(g_span + ((size_t)b * NSx + idx) * Dx))[t];
            acc.x += v.x; acc.y += v.y; acc.z += v.z; acc.w += v.w;
            cnt += 1.f;
        }
    }
    float inv = 1.f / fmaxf(cnt, 1.f);
    acc.x *= inv; acc.y *= inv; acc.z *= inv; acc.w *= inv;
    ((float4*)(g_vert + (size_t)bv * Dx))[t] = acc;
}

// ---------------------------------------------------------------------------
// Stage 3: feature assembly -> bf16 hi/lo split, K padded to 2368
// ---------------------------------------------------------------------------
__global__ void feat_kernel(const int* __restrict__ hti,
                            const int* __restrict__ dht,
                            const int* __restrict__ dth,
                            const float* __restrict__ dis) {
    int m = blockIdx.x;
    int b = m / Rx;
    int h  = hti[m * 2 + 0];
    int tl = hti[m * 2 + 1];
    const float* hp = g_vert + ((size_t)b * Vx + h)  * Dx;
    const float* tp = g_vert + ((size_t)b * Vx + tl) * Dx;
    const float* eh = dis + (size_t)dht[m] * DISx;
    const float* et = dis + (size_t)dth[m] * DISx;
    size_t rowoff = (size_t)m * KP;
    for (int k = threadIdx.x; k < KP; k += blockDim.x) {
        float v = 0.f;
        if (k < Dx)                 v = hp[k];
        else if (k < FINx)          v = eh[k - Dx];
        else if (k < FINx + Dx)     v = tp[k - FINx];
        else if (k < 2 * FINx)      v = et[k - FINx - Dx];
        else if (k < KF) { int q = k - 2 * FINx; v = hp[q] * tp[q]; }
        __nv_bfloat16 hi = __float2bfloat16(v);
        float lo = v - __bfloat162float(hi);
        g_ahi[rowoff + k] = hi;
        g_alo[rowoff + k] = __float2bfloat16(lo);
    }
}

// ---------------------------------------------------------------------------
// Stage 3b: W1 transpose + hi/lo split.  W1[K x 384] -> Bt[384 x KP]
// ---------------------------------------------------------------------------
__global__ void prep_w1(const float* __restrict__ W1) {
    int n = blockIdx.x;                       // 0..383
    size_t rowoff = (size_t)n * KP;
    for (int k = threadIdx.x; k < KP; k += blockDim.x) {
        float v = (k < KF) ? W1[(size_t)k * HIDx + n] : 0.f;
        __nv_bfloat16 hi = __float2bfloat16(v);
        float lo = v - __bfloat162float(hi);
        g_bhi[rowoff + k] = hi;
        g_blo[rowoff + k] = __float2bfloat16(lo);
    }
}

// ---------------------------------------------------------------------------
// Stage 4: GEMM1 via mma.sync (HMMA bf16, fp32 accum), hi/lo 3-stream.
//   D[8192x384] = A[8192xKP] * Bt^T.
//   BM=128, BN=64, BK=32; 8 warps, warp tile 32x32 (2 m-frags x 4 n-frags).
//   Grid (6, 64): n on blockIdx.x so the 6 CTAs sharing an A-tile are
//   id-adjacent -> co-scheduled -> A re-reads hit L2.
//   2 CTAs/SM (smem 60KB, ~95 regs) -> wave efficiency 65% -> ~87%.
//   Rows padded to 40 bf16 (80B stride) -> conflict-free ldmatrix.
// ---------------------------------------------------------------------------
#define PAD    40                       // bf16 elems per smem row
#define ARR_A  (128 * PAD * 2)          // 10240 B (Ahi / Alo)
#define ARR_Bb (64 * PAD * 2)           // 5120 B  (Bhi / Blo)
#define STG_B  (2 * ARR_A + 2 * ARR_Bb) // 30720 B per stage
#define G1_SMEM (2 * STG_B)             // 61440 B

__global__ __launch_bounds__(256, 2) void gemm1_mma() {
    extern __shared__ char smem[];
    uint32_t sb = smem_u32(smem);
    int t = threadIdx.x, wid = t >> 5, lane = t & 31;
    int n0 = blockIdx.x * 64;           // 6 n-blocks
    int m0 = blockIdx.y * 128;          // 64 m-blocks
    int wm = (wid & 3) * 32;            // warp m offset (0/32/64/96)
    int wn = (wid >> 2) * 32;           // warp n offset (0/32)

    float acc[2][4][4];
    #pragma unroll
    for (int i = 0; i < 2; i++)
        #pragma unroll
        for (int j = 0; j < 4; j++)
            #pragma unroll
            for (int q = 0; q < 4; q++) acc[i][j][q] = 0.f;

    // --- async tile loader: A 1024 + B 512 16B-chunks, 6 per thread ---
    auto load_chunk = [&](int k0, int s) {
        uint32_t stg = sb + (uint32_t)s * STG_B;
        #pragma unroll
        for (int i = 0; i < 4; i++) {               // A: ahi (i<2), alo (i>=2)
            int e = ((i & 1) << 8) + t;             // 0..511
            int r = e >> 2;                         // row 0..127
            int c = e & 3;                          // 16B chunk in row
            const __nv_bfloat16* base = (i < 2) ? g_ahi : g_alo;
            uint32_t aoff = (i < 2) ? 0u : (uint32_t)ARR_A;
            const __nv_bfloat16* src = base + (size_t)(m0 + r) * KP + k0 + c * 8;
            cp16(stg + aoff + r * (PAD * 2) + c * 16, src);
        }
        {                                           // B: 64 rows each array
            int r = t >> 2, c = t & 3;
            const __nv_bfloat16* sh = g_bhi + (size_t)(n0 + r) * KP + k0 + c * 8;
            const __nv_bfloat16* sl = g_blo + (size_t)(n0 + r) * KP + k0 + c * 8;
            cp16(stg + 2 * ARR_A +           r * (PAD * 2) + c * 16, sh);
            cp16(stg + 2 * ARR_A + ARR_Bb + r * (PAD * 2) + c * 16, sl);
        }
    };

    load_chunk(0, 0);
    CP_COMMIT();

    int lr = lane & 15;                 // ldmatrix row-within-frag
    int lc = lane >> 4;                 // ldmatrix 8-col group

    for (int c = 0; c < NCHUNK; c++) {
        int s = c & 1;
        if (c + 1 < NCHUNK) {
            load_chunk((c + 1) * BKx, s ^ 1);
            CP_COMMIT();
            CP_WAIT(1);
        } else {
            CP_WAIT(0);
        }
        __syncthreads();

        uint32_t a_base = sb + (uint32_t)s * STG_B;
        uint32_t b_base = a_base + 2 * ARR_A;

        #pragma unroll
        for (int ks = 0; ks < 2; ks++) {
            uint32_t koff = (uint32_t)(ks * 16 + lc * 8) * 2;
            uint32_t ahi[2][4], alo[2][4];
            #pragma unroll
            for (int mf = 0; mf < 2; mf++) {
                uint32_t ro = (uint32_t)(wm + mf * 16 + lr) * (PAD * 2) + koff;
                ldsm4(ahi[mf], a_base + ro);
                ldsm4(alo[mf], a_base + ARR_A + ro);
            }
            uint32_t bhi[8], blo[8];
            #pragma unroll
            for (int g = 0; g < 2; g++) {
                uint32_t ro = (uint32_t)(wn + g * 16 + lr) * (PAD * 2) + koff;
                ldsm4(&bhi[g * 4], b_base + ro);
                ldsm4(&blo[g * 4], b_base + ARR_Bb + ro);
            }
            // x4 of [n16][k16]: frag nf -> b0 = [(nf>>1)*4 + (nf&1)], b1 = +2
            #pragma unroll
            for (int mf = 0; mf < 2; mf++) {
                #pragma unroll
                for (int nf = 0; nf < 4; nf++) {
                    int bi = (nf >> 1) * 4 + (nf & 1);
                    mma_bf16(acc[mf][nf], ahi[mf], bhi[bi], bhi[bi + 2]);
                    mma_bf16(acc[mf][nf], ahi[mf], blo[bi], blo[bi + 2]);
                    mma_bf16(acc[mf][nf], alo[mf], bhi[bi], bhi[bi + 2]);
                }
            }
        }
        __syncthreads();
    }

    // Epilogue: ReLU, write g_hid (fp32)
    int row  = lane >> 2;
    int colp = (lane & 3) * 2;
    #pragma unroll
    for (int mf = 0; mf < 2; mf++) {
        #pragma unroll
        for (int nf = 0; nf < 4; nf++) {
            int r0 = m0 + wm + mf * 16 + row;
            int cc = n0 + wn + nf * 8 + colp;
            float2 v0, v1;
            v0.x = fmaxf(acc[mf][nf][0], 0.f);
            v0.y = fmaxf(acc[mf][nf][1], 0.f);
            v1.x = fmaxf(acc[mf][nf][2], 0.f);
            v1.y = fmaxf(acc[mf][nf][3], 0.f);
            *(float2*)(g_hid + (size_t)r0 * HIDx + cc)       = v0;
            *(float2*)(g_hid + (size_t)(r0 + 8) * HIDx + cc) = v1;
        }
    }
}

// ---------------------------------------------------------------------------
// Stage 5: GEMM2  hid (8192 x 384) @ W2 (384 x 97) + b2 -> out  (SIMT fp32)
// ---------------------------------------------------------------------------
#define G2_BM 128
#define G2_BN 64
#define G2_BK 8

__global__ __launch_bounds__(256) void gemm2_kernel(const float* __restrict__ W2,
                                                    const float* __restrict__ bias,
                                                    float* __restrict__ out) {
    __shared__ float As[G2_BK][132];
    __shared__ float Bs[G2_BK][G2_BN];

    int m0 = blockIdx.x * G2_BM;
    int n0 = blockIdx.y * G2_BN;
    int t  = threadIdx.x;
    int tx = t & 15;
    int ty = t >> 4;

    float acc[8][4];
    #pragma unroll
    for (int i = 0; i < 8; i++)
        #pragma unroll
        for (int j = 0; j < 4; j++) acc[i][j] = 0.f;

    int arow = t >> 1;
    int ac   = (t & 1) * 4;
    const float* Aptr = g_hid + (size_t)(m0 + arow) * HIDx + ac;

    for (int k0 = 0; k0 < HIDx; k0 += G2_BK) {
        float4 av = *(const float4*)(Aptr + k0);
        As[ac + 0][arow] = av.x;
        As[ac + 1][arow] = av.y;
        As[ac + 2][arow] = av.z;
        As[ac + 3][arow] = av.w;
        #pragma unroll
        for (int e = t; e < G2_BK * G2_BN; e += 256) {
            int kk = e >> 6, cc = e & 63;
            int n = n0 + cc;
            Bs[kk][cc] = (n < RELx) ? W2[(size_t)(k0 + kk) * RELx + n] : 0.f;
        }
        __syncthreads();
        #pragma unroll
        for (int kk = 0; kk < G2_BK; kk++) {
            float4 a0 = *(float4*)&As[kk][ty * 8];
            float4 a1 = *(float4*)&As[kk][ty * 8 + 4];
            float4 b0 = *(float4*)&Bs[kk][tx * 4];
            float a[8] = {a0.x, a0.y, a0.z, a0.w, a1.x, a1.y, a1.z, a1.w};
            float bb[4] = {b0.x, b0.y, b0.z, b0.w};
            #pragma unroll
            for (int i = 0; i < 8; i++)
                #pragma unroll
                for (int j = 0; j < 4; j++)
                    acc[i][j] += a[i] * bb[j];
        }
        __syncthreads();
    }

    #pragma unroll
    for (int i = 0; i < 8; i++) {
        int mm = m0 + ty * 8 + i;
        #pragma unroll
        for (int j = 0; j < 4; j++) {
            int n = n0 + tx * 4 + j;
            if (n < RELx)
                out[(size_t)mm * RELx + n] = acc[i][j] + bias[n];
        }
    }
}

// ---------------------------------------------------------------------------
// Launch
// ---------------------------------------------------------------------------
extern "C" void kernel_launch(void* const* d_in, const int* in_sizes, int n_in,
                              void* d_out, int out_size) {
    const float* sent  = (const float*)d_in[0];
    const int*   spans = (const int*)d_in[1];
    const int*   vidx  = (const int*)d_in[3];
    const int*   vmask = (const int*)d_in[4];
    const int*   hti   = (const int*)d_in[5];
    const int*   dht   = (const int*)d_in[7];
    const int*   dth   = (const int*)d_in[8];
    const float* dis   = (const float*)d_in[9];
    const float* W1    = (const float*)d_in[10];
    const float* W2    = (const float*)d_in[11];
    const float* b2    = (const float*)d_in[12];
    float* out = (float*)d_out;

    cudaFuncSetAttribute(gemm1_mma, cudaFuncAttributeMaxDynamicSharedMemorySize,
                         G1_SMEM);

    span_kernel<<<Bx * NSx, 192>>>(sent, spans);
    vertex_kernel<<<Bx * Vx, 192>>>(vidx, vmask);
    feat_kernel<<<MROWS, 256>>>(hti, dht, dth, dis);
    prep_w1<<<HIDx, 256>>>(W1);
    gemm1_mma<<<dim3(HIDx / 64, MROWS / 128), 256, G1_SMEM>>>();
    gemm2_kernel<<<dim3(MROWS / G2_BM, (RELx + G2_BN - 1) / G2_BN), 256>>>(W2, b2, out);
}

// round 9
// speedup vs baseline: 2.4573x; 1.4325x over previous
#include <cuda_runtime.h>
#include <cuda_bf16.h>
#include <cstdint>

// Problem constants
#define Bx    16
#define Sx    1024
#define Dx    768
#define NSx   256
#define MAXWx 8
#define Vx    128
#define Cx    6
#define Rx    512
#define RELx  97
#define HIDx  384
#define DISx  20
#define FINx  (Dx + DISx)          // 788
#define KF    (2 * FINx + Dx)      // 2344
#define MROWS (Bx * Rx)            // 8192
#define NVERT (Bx * Vx)            // 2048
#define KD    768                  // K of both GEMMs (24 * 32)
#define BKx   32
#define NCHUNK (KD / BKx)          // 24

// W1 row-block offsets: [head 0..767 | eh 768..787 | tail 788..1555 |
//                        et 1556..1575 | prod 1576..2343]
#define W1_EH   768
#define W1_TAIL 788
#define W1_ET   1556
#define W1_PROD 1576

// Scratch (static device globals — no allocation allowed)
__device__ float g_span[(size_t)Bx * NSx * Dx];
__device__ float g_vert[(size_t)NVERT * Dx];
__device__ __align__(16) __nv_bfloat16 g_vhi[(size_t)NVERT * KD];   // vertex hi
__device__ __align__(16) __nv_bfloat16 g_vlo[(size_t)NVERT * KD];   // vertex lo
__device__ __align__(16) __nv_bfloat16 g_phi[(size_t)MROWS * KD];   // head*tail hi
__device__ __align__(16) __nv_bfloat16 g_plo[(size_t)MROWS * KD];   // head*tail lo
__device__ __align__(16) __nv_bfloat16 g_bvhi[(size_t)768 * KD];    // [W1a|W1c]^T hi
__device__ __align__(16) __nv_bfloat16 g_bvlo[(size_t)768 * KD];
__device__ __align__(16) __nv_bfloat16 g_bphi[(size_t)HIDx * KD];   // W1e^T hi
__device__ __align__(16) __nv_bfloat16 g_bplo[(size_t)HIDx * KD];
__device__ float g_P[(size_t)NVERT * 768];                          // vertex proj
__device__ float g_e1[20 * HIDx];
__device__ float g_e2[20 * HIDx];
__device__ float g_hid[(size_t)MROWS * HIDx];

// ---------------------------------------------------------------------------
// PTX helpers (sm_80-era only — tcgen05 won't assemble for compute_103)
// ---------------------------------------------------------------------------
__device__ __forceinline__ uint32_t smem_u32(const void* p) {
    uint32_t a;
    asm("{ .reg .u64 t; cvta.to.shared.u64 t, %1; cvt.u32.u64 %0, t; }"
        : "=r"(a) : "l"(p));
    return a;
}

__device__ __forceinline__ void ldsm4(uint32_t* r, uint32_t addr) {
    asm volatile("ldmatrix.sync.aligned.m8n8.x4.shared.b16 {%0,%1,%2,%3}, [%4];"
                 : "=r"(r[0]), "=r"(r[1]), "=r"(r[2]), "=r"(r[3]) : "r"(addr));
}

__device__ __forceinline__ void mma_bf16(float* d, const uint32_t* a,
                                         uint32_t b0, uint32_t b1) {
    asm volatile(
        "mma.sync.aligned.m16n8k16.row.col.f32.bf16.bf16.f32 "
        "{%0,%1,%2,%3}, {%4,%5,%6,%7}, {%8,%9}, {%0,%1,%2,%3};"
        : "+f"(d[0]), "+f"(d[1]), "+f"(d[2]), "+f"(d[3])
        : "r"(a[0]), "r"(a[1]), "r"(a[2]), "r"(a[3]), "r"(b0), "r"(b1));
}

__device__ __forceinline__ void cp16(uint32_t dst, const void* src) {
    asm volatile("cp.async.cg.shared.global [%0], [%1], 16;"
                 :: "r"(dst), "l"(src));
}
#define CP_COMMIT() asm volatile("cp.async.commit_group;" ::: "memory")
#define CP_WAIT(n)  asm volatile("cp.async.wait_group %0;" :: "n"(n) : "memory")

__device__ __forceinline__ void split2(float a, float b,
                                       __nv_bfloat162* hi, __nv_bfloat162* lo) {
    __nv_bfloat16 ha = __float2bfloat16(a);
    __nv_bfloat16 hb = __float2bfloat16(b);
    *hi = __nv_bfloat162(ha, hb);
    *lo = __nv_bfloat162(__float2bfloat16(a - __bfloat162float(ha)),
                         __float2bfloat16(b - __bfloat162float(hb)));
}

// ---------------------------------------------------------------------------
// Stage 1: span max-pool
// ---------------------------------------------------------------------------
__global__ void span_kernel(const float* __restrict__ sent,
                            const int* __restrict__ spans) {
    int bs = blockIdx.x;
    int b  = bs / NSx;
    int start = spans[bs * 2 + 0];
    int end   = spans[bs * 2 + 1];
    int w = end - start;
    const float4* base = (const float4*)(sent + ((size_t)b * Sx + start) * Dx);
    int t = threadIdx.x;
    float4 m = base[t];
    for (int j = 1; j <= w; j++) {
        float4 v = base[(size_t)j * (Dx / 4) + t];
        m.x = fmaxf(m.x, v.x); m.y = fmaxf(m.y, v.y);
        m.z = fmaxf(m.z, v.z); m.w = fmaxf(m.w, v.w);
    }
    ((float4*)(g_span + (size_t)bs * Dx))[t] = m;
}

// ---------------------------------------------------------------------------
// Stage 2: vertex masked mean (fp32 + bf16 hi/lo for GEMM_V)
// ---------------------------------------------------------------------------
__global__ void vertex_kernel(const int* __restrict__ vidx,
                              const int* __restrict__ vmask) {
    int bv = blockIdx.x;              // b*V + v  (0..2047)
    int b  = bv / Vx;
    int t  = threadIdx.x;             // 0..191
    float4 acc = make_float4(0.f, 0.f, 0.f, 0.f);
    float cnt = 0.f;
    #pragma unroll
    for (int c = 0; c < Cx; c++) {
        int mk = vmask[bv * Cx + c];
        if (mk) {
            int idx = vidx[bv * Cx + c];
            float4 v = ((const float4*)(g_span + ((size_t)b * NSx + idx) * Dx))[t];
            acc.x += v.x; acc.y += v.y; acc.z += v.z; acc.w += v.w;
            cnt += 1.f;
        }
    }
    float inv = 1.f / fmaxf(cnt, 1.f);
    acc.x *= inv; acc.y *= inv; acc.z *= inv; acc.w *= inv;
    ((float4*)(g_vert + (size_t)bv * Dx))[t] = acc;

    __nv_bfloat162 h0, l0, h1, l1;
    split2(acc.x, acc.y, &h0, &l0);
    split2(acc.z, acc.w, &h1, &l1);
    size_t o2 = (size_t)bv * (KD / 2) + t * 2;
    ((__nv_bfloat162*)g_vhi)[o2]     = h0;
    ((__nv_bfloat162*)g_vhi)[o2 + 1] = h1;
    ((__nv_bfloat162*)g_vlo)[o2]     = l0;
    ((__nv_bfloat162*)g_vlo)[o2 + 1] = l1;
}

// ---------------------------------------------------------------------------
// Stage 3: product features  head∘tail -> bf16 hi/lo  (8192 x 768)
// ---------------------------------------------------------------------------
__global__ void feat_prod(const int* __restrict__ hti) {
    int m = blockIdx.x;
    int b = m / Rx;
    int h  = hti[m * 2 + 0];
    int tl = hti[m * 2 + 1];
    const float4* hp = (const float4*)(g_vert + ((size_t)b * Vx + h)  * Dx);
    const float4* tp = (const float4*)(g_vert + ((size_t)b * Vx + tl) * Dx);
    int t = threadIdx.x;              // 0..191
    float4 a = hp[t], c = tp[t];
    float4 p = make_float4(a.x * c.x, a.y * c.y, a.z * c.z, a.w * c.w);
    __nv_bfloat162 h0, l0, h1, l1;
    split2(p.x, p.y, &h0, &l0);
    split2(p.z, p.w, &h1, &l1);
    size_t o2 = (size_t)m * (KD / 2) + t * 2;
    ((__nv_bfloat162*)g_phi)[o2]     = h0;
    ((__nv_bfloat162*)g_phi)[o2 + 1] = h1;
    ((__nv_bfloat162*)g_plo)[o2]     = l0;
    ((__nv_bfloat162*)g_plo)[o2 + 1] = l1;
}

// ---------------------------------------------------------------------------
// Stage 3b: weight prep.  Bv[768 x 768] = [W1a|W1c]^T ; Bp[384 x 768] = W1e^T
// grid 1152 rows; W1 is [KF x 384] row-major.
// ---------------------------------------------------------------------------
__global__ void prep_w(const float* __restrict__ W1) {
    int row = blockIdx.x;
    for (int k = threadIdx.x; k < KD; k += blockDim.x) {
        float v;
        __nv_bfloat16* dh;
        __nv_bfloat16* dl;
        size_t off;
        if (row < 768) {
            v = (row < HIDx) ? W1[(size_t)k * HIDx + row]
                             : W1[(size_t)(W1_TAIL + k) * HIDx + (row - HIDx)];
            off = (size_t)row * KD + k;
            dh = g_bvhi; dl = g_bvlo;
        } else {
            int n = row - 768;
            v = W1[(size_t)(W1_PROD + k) * HIDx + n];
            off = (size_t)n * KD + k;
            dh = g_bphi; dl = g_bplo;
        }
        __nv_bfloat16 hi = __float2bfloat16(v);
        dh[off] = hi;
        dl[off] = __float2bfloat16(v - __bfloat162float(hi));
    }
}

// ---------------------------------------------------------------------------
// Stage 3c: distance tables.  E1/E2[20 x 384] fp32 (exact).
// grid (20, 2), block 384.
// ---------------------------------------------------------------------------
__global__ void e_table(const float* __restrict__ dis,
                        const float* __restrict__ W1) {
    int d = blockIdx.x;
    int which = blockIdx.y;           // 0 -> eh (W1b), 1 -> et (W1d)
    int n = threadIdx.x;
    int wbase = which ? W1_ET : W1_EH;
    float s = 0.f;
    #pragma unroll
    for (int j = 0; j < DISx; j++)
        s += dis[d * DISx + j] * W1[(size_t)(wbase + j) * HIDx + n];
    (which ? g_e2 : g_e1)[d * HIDx + n] = s;
}

// ---------------------------------------------------------------------------
// Generic hi/lo bf16 HMMA GEMM: out[M x N] = A[M x 768] * B[N x 768]^T
//   3 streams AhiBhi + AhiBlo + AloBhi, fp32 accum.
//   BM=128, BN=64, BK=32; 8 warps (warp 32x32); 2 CTAs/SM.
//   gather!=0: epilogue adds P/E1/E2 gathered terms + ReLU (GEMM_P -> g_hid)
// ---------------------------------------------------------------------------
#define PAD    40                       // bf16 elems per smem row (80B stride)
#define ARR_A  (128 * PAD * 2)          // 10240 B
#define ARR_Bb (64 * PAD * 2)           // 5120 B
#define STG_B  (2 * ARR_A + 2 * ARR_Bb) // 30720 B
#define G1_SMEM (2 * STG_B)             // 61440 B

__global__ __launch_bounds__(256, 2) void gemm_hilo(
    const __nv_bfloat16* __restrict__ Ahi, const __nv_bfloat16* __restrict__ Alo,
    const __nv_bfloat16* __restrict__ Bhi, const __nv_bfloat16* __restrict__ Blo,
    float* __restrict__ out, int ldc, int gather,
    const int* __restrict__ hti, const int* __restrict__ dht,
    const int* __restrict__ dth) {
    extern __shared__ char smem[];
    uint32_t sb = smem_u32(smem);
    int t = threadIdx.x, wid = t >> 5, lane = t & 31;
    int n0 = blockIdx.x * 64;
    int m0 = blockIdx.y * 128;
    int wm = (wid & 3) * 32;
    int wn = (wid >> 2) * 32;

    float acc[2][4][4];
    #pragma unroll
    for (int i = 0; i < 2; i++)
        #pragma unroll
        for (int j = 0; j < 4; j++)
            #pragma unroll
            for (int q = 0; q < 4; q++) acc[i][j][q] = 0.f;

    auto load_chunk = [&](int k0, int s) {
        uint32_t stg = sb + (uint32_t)s * STG_B;
        #pragma unroll
        for (int i = 0; i < 4; i++) {               // A: hi (i<2), lo (i>=2)
            int e = ((i & 1) << 8) + t;
            int r = e >> 2;
            int c = e & 3;
            const __nv_bfloat16* base = (i < 2) ? Ahi : Alo;
            uint32_t aoff = (i < 2) ? 0u : (uint32_t)ARR_A;
            cp16(stg + aoff + r * (PAD * 2) + c * 16,
                 base + (size_t)(m0 + r) * KD + k0 + c * 8);
        }
        {                                           // B
            int r = t >> 2, c = t & 3;
            cp16(stg + 2 * ARR_A +          r * (PAD * 2) + c * 16,
                 Bhi + (size_t)(n0 + r) * KD + k0 + c * 8);
            cp16(stg + 2 * ARR_A + ARR_Bb + r * (PAD * 2) + c * 16,
                 Blo + (size_t)(n0 + r) * KD + k0 + c * 8);
        }
    };

    load_chunk(0, 0);
    CP_COMMIT();

    int lr = lane & 15;
    int lc = lane >> 4;

    for (int c = 0; c < NCHUNK; c++) {
        int s = c & 1;
        if (c + 1 < NCHUNK) {
            load_chunk((c + 1) * BKx, s ^ 1);
            CP_COMMIT();
            CP_WAIT(1);
        } else {
            CP_WAIT(0);
        }
        __syncthreads();

        uint32_t a_base = sb + (uint32_t)s * STG_B;
        uint32_t b_base = a_base + 2 * ARR_A;

        #pragma unroll
        for (int ks = 0; ks < 2; ks++) {
            uint32_t koff = (uint32_t)(ks * 16 + lc * 8) * 2;
            uint32_t ahi[2][4], alo[2][4];
            #pragma unroll
            for (int mf = 0; mf < 2; mf++) {
                uint32_t ro = (uint32_t)(wm + mf * 16 + lr) * (PAD * 2) + koff;
                ldsm4(ahi[mf], a_base + ro);
                ldsm4(alo[mf], a_base + ARR_A + ro);
            }
            uint32_t bhi[8], blo[8];
            #pragma unroll
            for (int g = 0; g < 2; g++) {
                uint32_t ro = (uint32_t)(wn + g * 16 + lr) * (PAD * 2) + koff;
                ldsm4(&bhi[g * 4], b_base + ro);
                ldsm4(&blo[g * 4], b_base + ARR_Bb + ro);
            }
            #pragma unroll
            for (int mf = 0; mf < 2; mf++) {
                #pragma unroll
                for (int nf = 0; nf < 4; nf++) {
                    int bi = (nf >> 1) * 4 + (nf & 1);
                    mma_bf16(acc[mf][nf], ahi[mf], bhi[bi], bhi[bi + 2]);
                    mma_bf16(acc[mf][nf], ahi[mf], blo[bi], blo[bi + 2]);
                    mma_bf16(acc[mf][nf], alo[mf], bhi[bi], bhi[bi + 2]);
                }
            }
        }
        __syncthreads();
    }

    int row  = lane >> 2;
    int colp = (lane & 3) * 2;
    if (!gather) {
        // Plain fp32 store (GEMM_V -> P)
        #pragma unroll
        for (int mf = 0; mf < 2; mf++) {
            #pragma unroll
            for (int nf = 0; nf < 4; nf++) {
                int r0 = m0 + wm + mf * 16 + row;
                int cc = n0 + wn + nf * 8 + colp;
                *(float2*)(out + (size_t)r0 * ldc + cc) =
                    make_float2(acc[mf][nf][0], acc[mf][nf][1]);
                *(float2*)(out + (size_t)(r0 + 8) * ldc + cc) =
                    make_float2(acc[mf][nf][2], acc[mf][nf][3]);
            }
        }
    } else {
        // GEMM_P epilogue: + P[h] + P[t] + E1 + E2, ReLU -> g_hid
        #pragma unroll
        for (int mf = 0; mf < 2; mf++) {
            #pragma unroll
            for (int rr = 0; rr < 2; rr++) {
                int r = m0 + wm + mf * 16 + row + rr * 8;
                int b = r / Rx;
                int hrow = b * Vx + hti[r * 2 + 0];
                int trow = b * Vx + hti[r * 2 + 1];
                const float* ph = g_P + (size_t)hrow * 768;
                const float* pt = g_P + (size_t)trow * 768 + HIDx;
                const float* e1 = g_e1 + dht[r] * HIDx;
                const float* e2 = g_e2 + dth[r] * HIDx;
                #pragma unroll
                for (int nf = 0; nf < 4; nf++) {
                    int cc = n0 + wn + nf * 8 + colp;
                    float2 a0 = *(const float2*)(ph + cc);
                    float2 a1 = *(const float2*)(pt + cc);
                    float2 a2 = *(const float2*)(e1 + cc);
                    float2 a3 = *(const float2*)(e2 + cc);
                    float v0 = acc[mf][nf][rr * 2 + 0] + a0.x + a1.x + a2.x + a3.x;
                    float v1 = acc[mf][nf][rr * 2 + 1] + a0.y + a1.y + a2.y + a3.y;
                    *(float2*)(out + (size_t)r * ldc + cc) =
                        make_float2(fmaxf(v0, 0.f), fmaxf(v1, 0.f));
                }
            }
        }
    }
}

// ---------------------------------------------------------------------------
// Stage 5: GEMM2  hid (8192 x 384) @ W2 (384 x 97) + b2 -> out  (SIMT fp32)
// ---------------------------------------------------------------------------
#define G2_BM 128
#define G2_BN 64
#define G2_BK 8

__global__ __launch_bounds__(256) void gemm2_kernel(const float* __restrict__ W2,
                                                    const float* __restrict__ bias,
                                                    float* __restrict__ out) {
    __shared__ float As[G2_BK][132];
    __shared__ float Bs[G2_BK][G2_BN];

    int m0 = blockIdx.x * G2_BM;
    int n0 = blockIdx.y * G2_BN;
    int t  = threadIdx.x;
    int tx = t & 15;
    int ty = t >> 4;

    float acc[8][4];
    #pragma unroll
    for (int i = 0; i < 8; i++)
        #pragma unroll
        for (int j = 0; j < 4; j++) acc[i][j] = 0.f;

    int arow = t >> 1;
    int ac   = (t & 1) * 4;
    const float* Aptr = g_hid + (size_t)(m0 + arow) * HIDx + ac;

    for (int k0 = 0; k0 < HIDx; k0 += G2_BK) {
        float4 av = *(const float4*)(Aptr + k0);
        As[ac + 0][arow] = av.x;
        As[ac + 1][arow] = av.y;
        As[ac + 2][arow] = av.z;
        As[ac + 3][arow] = av.w;
        #pragma unroll
        for (int e = t; e < G2_BK * G2_BN; e += 256) {
            int kk = e >> 6, cc = e & 63;
            int n = n0 + cc;
            Bs[kk][cc] = (n < RELx) ? W2[(size_t)(k0 + kk) * RELx + n] : 0.f;
        }
        __syncthreads();
        #pragma unroll
        for (int kk = 0; kk < G2_BK; kk++) {
            float4 a0 = *(float4*)&As[kk][ty * 8];
            float4 a1 = *(float4*)&As[kk][ty * 8 + 4];
            float4 b0 = *(float4*)&Bs[kk][tx * 4];
            float a[8] = {a0.x, a0.y, a0.z, a0.w, a1.x, a1.y, a1.z, a1.w};
            float bb[4] = {b0.x, b0.y, b0.z, b0.w};
            #pragma unroll
            for (int i = 0; i < 8; i++)
                #pragma unroll
                for (int j = 0; j < 4; j++)
                    acc[i][j] += a[i] * bb[j];
        }
        __syncthreads();
    }

    #pragma unroll
    for (int i = 0; i < 8; i++) {
        int mm = m0 + ty * 8 + i;
        #pragma unroll
        for (int j = 0; j < 4; j++) {
            int n = n0 + tx * 4 + j;
            if (n < RELx)
                out[(size_t)mm * RELx + n] = acc[i][j] + bias[n];
        }
    }
}

// ---------------------------------------------------------------------------
// Launch
// ---------------------------------------------------------------------------
extern "C" void kernel_launch(void* const* d_in, const int* in_sizes, int n_in,
                              void* d_out, int out_size) {
    const float* sent  = (const float*)d_in[0];
    const int*   spans = (const int*)d_in[1];
    const int*   vidx  = (const int*)d_in[3];
    const int*   vmask = (const int*)d_in[4];
    const int*   hti   = (const int*)d_in[5];
    const int*   dht   = (const int*)d_in[7];
    const int*   dth   = (const int*)d_in[8];
    const float* dis   = (const float*)d_in[9];
    const float* W1    = (const float*)d_in[10];
    const float* W2    = (const float*)d_in[11];
    const float* b2    = (const float*)d_in[12];
    float* out = (float*)d_out;

    cudaFuncSetAttribute(gemm_hilo, cudaFuncAttributeMaxDynamicSharedMemorySize,
                         G1_SMEM);

    span_kernel<<<Bx * NSx, 192>>>(sent, spans);
    vertex_kernel<<<NVERT, 192>>>(vidx, vmask);
    feat_prod<<<MROWS, 192>>>(hti);
    prep_w<<<1152, 256>>>(W1);
    e_table<<<dim3(20, 2), HIDx>>>(dis, W1);

    __nv_bfloat16 *p_vhi, *p_vlo, *p_phi, *p_plo;
    __nv_bfloat16 *p_bvhi, *p_bvlo, *p_bphi, *p_bplo;
    float *p_P, *p_hid;
    cudaGetSymbolAddress((void**)&p_vhi,  g_vhi);
    cudaGetSymbolAddress((void**)&p_vlo,  g_vlo);
    cudaGetSymbolAddress((void**)&p_phi,  g_phi);
    cudaGetSymbolAddress((void**)&p_plo,  g_plo);
    cudaGetSymbolAddress((void**)&p_bvhi, g_bvhi);
    cudaGetSymbolAddress((void**)&p_bvlo, g_bvlo);
    cudaGetSymbolAddress((void**)&p_bphi, g_bphi);
    cudaGetSymbolAddress((void**)&p_bplo, g_bplo);
    cudaGetSymbolAddress((void**)&p_P,    g_P);
    cudaGetSymbolAddress((void**)&p_hid,  g_hid);

    // GEMM_V: P[2048 x 768] = vertex_emb @ [W1a|W1c]
    gemm_hilo<<<dim3(768 / 64, NVERT / 128), 256, G1_SMEM>>>(
        p_vhi, p_vlo, p_bvhi, p_bvlo, p_P, 768, 0, nullptr, nullptr, nullptr);
    // GEMM_P: hid = relu(prod @ W1e + gathered terms)
    gemm_hilo<<<dim3(HIDx / 64, MROWS / 128), 256, G1_SMEM>>>(
        p_phi, p_plo, p_bphi, p_bplo, p_hid, HIDx, 1, hti, dht, dth);

    gemm2_kernel<<<dim3(MROWS / G2_BM, (RELx + G2_BN - 1) / G2_BN), 256>>>(W2, b2, out);
}

// round 10
// speedup vs baseline: 3.0505x; 1.2414x over previous
#include <cuda_runtime.h>
#include <cuda_bf16.h>
#include <cstdint>

// Problem constants
#define Bx    16
#define Sx    1024
#define Dx    768
#define NSx   256
#define MAXWx 8
#define Vx    128
#define Cx    6
#define Rx    512
#define RELx  97
#define HIDx  384
#define DISx  20
#define FINx  (Dx + DISx)          // 788
#define KF    (2 * FINx + Dx)      // 2344
#define MROWS (Bx * Rx)            // 8192
#define NVERT (Bx * Vx)            // 2048
#define KD    768                  // K of the two big GEMMs
#define BKx   32

// W1 row-block offsets: [head 0..767 | eh 768..787 | tail 788..1555 |
//                        et 1556..1575 | prod 1576..2343]
#define W1_EH   768
#define W1_TAIL 788
#define W1_ET   1556
#define W1_PROD 1576

// Scratch (static device globals — no allocation allowed)
__device__ float g_span[(size_t)Bx * NSx * Dx];
__device__ float g_vert[(size_t)NVERT * Dx];
__device__ __align__(16) __nv_bfloat16 g_vhi[(size_t)NVERT * KD];
__device__ __align__(16) __nv_bfloat16 g_vlo[(size_t)NVERT * KD];
__device__ __align__(16) __nv_bfloat16 g_phi[(size_t)MROWS * KD];
__device__ __align__(16) __nv_bfloat16 g_plo[(size_t)MROWS * KD];
__device__ __align__(16) __nv_bfloat16 g_bvhi[(size_t)768 * KD];    // [W1a|W1c]^T
__device__ __align__(16) __nv_bfloat16 g_bvlo[(size_t)768 * KD];
__device__ __align__(16) __nv_bfloat16 g_bphi[(size_t)HIDx * KD];   // W1e^T
__device__ __align__(16) __nv_bfloat16 g_bplo[(size_t)HIDx * KD];
__device__ __align__(16) __nv_bfloat16 g_hhi[(size_t)MROWS * HIDx]; // hid hi
__device__ __align__(16) __nv_bfloat16 g_hlo[(size_t)MROWS * HIDx]; // hid lo
__device__ __align__(16) __nv_bfloat16 g_w2hi[(size_t)128 * HIDx];  // W2^T padded
__device__ __align__(16) __nv_bfloat16 g_w2lo[(size_t)128 * HIDx];
__device__ float g_P[(size_t)NVERT * 768];                          // vertex proj
__device__ float g_e1[20 * HIDx];
__device__ float g_e2[20 * HIDx];

// ---------------------------------------------------------------------------
// PTX helpers (sm_80-era only — tcgen05 won't assemble for compute_103)
// ---------------------------------------------------------------------------
__device__ __forceinline__ uint32_t smem_u32(const void* p) {
    uint32_t a;
    asm("{ .reg .u64 t; cvta.to.shared.u64 t, %1; cvt.u32.u64 %0, t; }"
        : "=r"(a) : "l"(p));
    return a;
}

__device__ __forceinline__ void ldsm4(uint32_t* r, uint32_t addr) {
    asm volatile("ldmatrix.sync.aligned.m8n8.x4.shared.b16 {%0,%1,%2,%3}, [%4];"
                 : "=r"(r[0]), "=r"(r[1]), "=r"(r[2]), "=r"(r[3]) : "r"(addr));
}

__device__ __forceinline__ void mma_bf16(float* d, const uint32_t* a,
                                         uint32_t b0, uint32_t b1) {
    asm volatile(
        "mma.sync.aligned.m16n8k16.row.col.f32.bf16.bf16.f32 "
        "{%0,%1,%2,%3}, {%4,%5,%6,%7}, {%8,%9}, {%0,%1,%2,%3};"
        : "+f"(d[0]), "+f"(d[1]), "+f"(d[2]), "+f"(d[3])
        : "r"(a[0]), "r"(a[1]), "r"(a[2]), "r"(a[3]), "r"(b0), "r"(b1));
}

__device__ __forceinline__ void cp16(uint32_t dst, const void* src) {
    asm volatile("cp.async.cg.shared.global [%0], [%1], 16;"
                 :: "r"(dst), "l"(src));
}
#define CP_COMMIT() asm volatile("cp.async.commit_group;" ::: "memory")
#define CP_WAIT(n)  asm volatile("cp.async.wait_group %0;" :: "n"(n) : "memory")

__device__ __forceinline__ void split2(float a, float b,
                                       __nv_bfloat162* hi, __nv_bfloat162* lo) {
    __nv_bfloat16 ha = __float2bfloat16(a);
    __nv_bfloat16 hb = __float2bfloat16(b);
    *hi = __nv_bfloat162(ha, hb);
    *lo = __nv_bfloat162(__float2bfloat16(a - __bfloat162float(ha)),
                         __float2bfloat16(b - __bfloat162float(hb)));
}

// ---------------------------------------------------------------------------
// Stage 1: span max-pool
// ---------------------------------------------------------------------------
__global__ void span_kernel(const float* __restrict__ sent,
                            const int* __restrict__ spans) {
    int bs = blockIdx.x;
    int b  = bs / NSx;
    int start = spans[bs * 2 + 0];
    int end   = spans[bs * 2 + 1];
    int w = end - start;
    const float4* base = (const float4*)(sent + ((size_t)b * Sx + start) * Dx);
    int t = threadIdx.x;
    float4 m = base[t];
    for (int j = 1; j <= w; j++) {
        float4 v = base[(size_t)j * (Dx / 4) + t];
        m.x = fmaxf(m.x, v.x); m.y = fmaxf(m.y, v.y);
        m.z = fmaxf(m.z, v.z); m.w = fmaxf(m.w, v.w);
    }
    ((float4*)(g_span + (size_t)bs * Dx))[t] = m;
}

// ---------------------------------------------------------------------------
// Stage 2: vertex masked mean (fp32 + bf16 hi/lo for GEMM_V)
// ---------------------------------------------------------------------------
__global__ void vertex_kernel(const int* __restrict__ vidx,
                              const int* __restrict__ vmask) {
    int bv = blockIdx.x;
    int b  = bv / Vx;
    int t  = threadIdx.x;             // 0..191
    float4 acc = make_float4(0.f, 0.f, 0.f, 0.f);
    float cnt = 0.f;
    #pragma unroll
    for (int c = 0; c < Cx; c++) {
        int mk = vmask[bv * Cx + c];
        if (mk) {
            int idx = vidx[bv * Cx + c];
            float4 v = ((const float4*)(g_span + ((size_t)b * NSx + idx) * Dx))[t];
            acc.x += v.x; acc.y += v.y; acc.z += v.z; acc.w += v.w;
            cnt += 1.f;
        }
    }
    float inv = 1.f / fmaxf(cnt, 1.f);
    acc.x *= inv; acc.y *= inv; acc.z *= inv; acc.w *= inv;
    ((float4*)(g_vert + (size_t)bv * Dx))[t] = acc;

    __nv_bfloat162 h0, l0, h1, l1;
    split2(acc.x, acc.y, &h0, &l0);
    split2(acc.z, acc.w, &h1, &l1);
    size_t o2 = (size_t)bv * (KD / 2) + t * 2;
    ((__nv_bfloat162*)g_vhi)[o2]     = h0;
    ((__nv_bfloat162*)g_vhi)[o2 + 1] = h1;
    ((__nv_bfloat162*)g_vlo)[o2]     = l0;
    ((__nv_bfloat162*)g_vlo)[o2 + 1] = l1;
}

// ---------------------------------------------------------------------------
// Stage 3: product features  head∘tail -> bf16 hi/lo  (8192 x 768)
// ---------------------------------------------------------------------------
__global__ void feat_prod(const int* __restrict__ hti) {
    int m = blockIdx.x;
    int b = m / Rx;
    int h  = hti[m * 2 + 0];
    int tl = hti[m * 2 + 1];
    const float4* hp = (const float4*)(g_vert + ((size_t)b * Vx + h)  * Dx);
    const float4* tp = (const float4*)(g_vert + ((size_t)b * Vx + tl) * Dx);
    int t = threadIdx.x;              // 0..191
    float4 a = hp[t], c = tp[t];
    float4 p = make_float4(a.x * c.x, a.y * c.y, a.z * c.z, a.w * c.w);
    __nv_bfloat162 h0, l0, h1, l1;
    split2(p.x, p.y, &h0, &l0);
    split2(p.z, p.w, &h1, &l1);
    size_t o2 = (size_t)m * (KD / 2) + t * 2;
    ((__nv_bfloat162*)g_phi)[o2]     = h0;
    ((__nv_bfloat162*)g_phi)[o2 + 1] = h1;
    ((__nv_bfloat162*)g_plo)[o2]     = l0;
    ((__nv_bfloat162*)g_plo)[o2 + 1] = l1;
}

// ---------------------------------------------------------------------------
// Stage 3b: weight prep.  Bv[768 x 768] = [W1a|W1c]^T ; Bp[384 x 768] = W1e^T
// ---------------------------------------------------------------------------
__global__ void prep_w(const float* __restrict__ W1) {
    int row = blockIdx.x;
    for (int k = threadIdx.x; k < KD; k += blockDim.x) {
        float v;
        __nv_bfloat16* dh;
        __nv_bfloat16* dl;
        size_t off;
        if (row < 768) {
            v = (row < HIDx) ? W1[(size_t)k * HIDx + row]
                             : W1[(size_t)(W1_TAIL + k) * HIDx + (row - HIDx)];
            off = (size_t)row * KD + k;
            dh = g_bvhi; dl = g_bvlo;
        } else {
            int n = row - 768;
            v = W1[(size_t)(W1_PROD + k) * HIDx + n];
            off = (size_t)n * KD + k;
            dh = g_bphi; dl = g_bplo;
        }
        __nv_bfloat16 hi = __float2bfloat16(v);
        dh[off] = hi;
        dl[off] = __float2bfloat16(v - __bfloat162float(hi));
    }
}

// Stage 3b': W2^T padded to 128 rows, hi/lo.  W2 is [384 x 97] row-major.
__global__ void prep_w2(const float* __restrict__ W2) {
    int n = blockIdx.x;                       // 0..127
    size_t rowoff = (size_t)n * HIDx;
    for (int k = threadIdx.x; k < HIDx; k += blockDim.x) {
        float v = (n < RELx) ? W2[(size_t)k * RELx + n] : 0.f;
        __nv_bfloat16 hi = __float2bfloat16(v);
        g_w2hi[rowoff + k] = hi;
        g_w2lo[rowoff + k] = __float2bfloat16(v - __bfloat162float(hi));
    }
}

// ---------------------------------------------------------------------------
// Stage 3c: distance tables.  E1/E2[20 x 384] fp32 (exact).
// ---------------------------------------------------------------------------
__global__ void e_table(const float* __restrict__ dis,
                        const float* __restrict__ W1) {
    int d = blockIdx.x;
    int which = blockIdx.y;           // 0 -> eh (W1b), 1 -> et (W1d)
    int n = threadIdx.x;
    int wbase = which ? W1_ET : W1_EH;
    float s = 0.f;
    #pragma unroll
    for (int j = 0; j < DISx; j++)
        s += dis[d * DISx + j] * W1[(size_t)(wbase + j) * HIDx + n];
    (which ? g_e2 : g_e1)[d * HIDx + n] = s;
}

// ---------------------------------------------------------------------------
// Generic hi/lo bf16 HMMA GEMM: out[M x N] = A[M x K] * B[N x K]^T
//   3 streams AhiBhi + AhiBlo + AloBhi, fp32 accum.
//   BM=128, BN=NF*16; 8 warps (4m x 2n, warp tile 32 x NF*8); 2 CTAs/SM.
//   MODE 0: plain fp32 store (GEMM_V -> P)
//   MODE 1: + gathered P/E1/E2 terms, ReLU, bf16 hi/lo store (GEMM_P -> hid)
//   MODE 2: + bias, n<RELx guard, fp32 store (GEMM2 -> out)
// ---------------------------------------------------------------------------
#define PAD    40                       // bf16 elems per smem row (80B stride)

template <int NF, int MODE>
__global__ __launch_bounds__(256, 2) void gemm_hilo(
    const __nv_bfloat16* __restrict__ Ahi, const __nv_bfloat16* __restrict__ Alo,
    const __nv_bfloat16* __restrict__ Bhi, const __nv_bfloat16* __restrict__ Blo,
    float* __restrict__ out, int ldc, int K, int nch,
    const int* __restrict__ hti, const int* __restrict__ dht,
    const int* __restrict__ dth, const float* __restrict__ bias) {
    constexpr int BN    = NF * 16;
    constexpr int ARR_A = 128 * PAD * 2;
    constexpr int ARR_B = BN * PAD * 2;
    constexpr int STG   = 2 * ARR_A + 2 * ARR_B;

    extern __shared__ char smem[];
    uint32_t sb = smem_u32(smem);
    int t = threadIdx.x, wid = t >> 5, lane = t & 31;
    int n0 = blockIdx.x * BN;
    int m0 = blockIdx.y * 128;
    int wm = (wid & 3) * 32;
    int wn = (wid >> 2) * (NF * 8);

    float acc[2][NF][4];
    #pragma unroll
    for (int i = 0; i < 2; i++)
        #pragma unroll
        for (int j = 0; j < NF; j++)
            #pragma unroll
            for (int q = 0; q < 4; q++) acc[i][j][q] = 0.f;

    auto load_chunk = [&](int k0, int s) {
        uint32_t stg = sb + (uint32_t)s * STG;
        #pragma unroll
        for (int i = 0; i < 4; i++) {               // A: hi (i<2), lo (i>=2)
            int e = ((i & 1) << 8) + t;
            int r = e >> 2;
            int c = e & 3;
            const __nv_bfloat16* base = (i < 2) ? Ahi : Alo;
            uint32_t aoff = (i < 2) ? 0u : (uint32_t)ARR_A;
            cp16(stg + aoff + r * (PAD * 2) + c * 16,
                 base + (size_t)(m0 + r) * K + k0 + c * 8);
        }
        if (t < BN * 4) {                           // B
            int r = t >> 2, c = t & 3;
            cp16(stg + 2 * ARR_A +         r * (PAD * 2) + c * 16,
                 Bhi + (size_t)(n0 + r) * K + k0 + c * 8);
            cp16(stg + 2 * ARR_A + ARR_B + r * (PAD * 2) + c * 16,
                 Blo + (size_t)(n0 + r) * K + k0 + c * 8);
        }
    };

    load_chunk(0, 0);
    CP_COMMIT();

    int lr = lane & 15;
    int lc = lane >> 4;

    for (int c = 0; c < nch; c++) {
        int s = c & 1;
        if (c + 1 < nch) {
            load_chunk((c + 1) * BKx, s ^ 1);
            CP_COMMIT();
            CP_WAIT(1);
        } else {
            CP_WAIT(0);
        }
        __syncthreads();

        uint32_t a_base = sb + (uint32_t)s * STG;
        uint32_t b_base = a_base + 2 * ARR_A;

        #pragma unroll
        for (int ks = 0; ks < 2; ks++) {
            uint32_t koff = (uint32_t)(ks * 16 + lc * 8) * 2;
            uint32_t ahi[2][4], alo[2][4];
            #pragma unroll
            for (int mf = 0; mf < 2; mf++) {
                uint32_t ro = (uint32_t)(wm + mf * 16 + lr) * (PAD * 2) + koff;
                ldsm4(ahi[mf], a_base + ro);
                ldsm4(alo[mf], a_base + ARR_A + ro);
            }
            uint32_t bhi[NF * 2], blo[NF * 2];
            #pragma unroll
            for (int g = 0; g < NF / 2; g++) {
                uint32_t ro = (uint32_t)(wn + g * 16 + lr) * (PAD * 2) + koff;
                ldsm4(&bhi[g * 4], b_base + ro);
                ldsm4(&blo[g * 4], b_base + ARR_B + ro);
            }
            #pragma unroll
            for (int mf = 0; mf < 2; mf++) {
                #pragma unroll
                for (int nf = 0; nf < NF; nf++) {
                    int bi = (nf >> 1) * 4 + (nf & 1);
                    mma_bf16(acc[mf][nf], ahi[mf], bhi[bi], bhi[bi + 2]);
                    mma_bf16(acc[mf][nf], ahi[mf], blo[bi], blo[bi + 2]);
                    mma_bf16(acc[mf][nf], alo[mf], bhi[bi], bhi[bi + 2]);
                }
            }
        }
        __syncthreads();
    }

    int row  = lane >> 2;
    int colp = (lane & 3) * 2;
    if (MODE == 0) {
        #pragma unroll
        for (int mf = 0; mf < 2; mf++) {
            #pragma unroll
            for (int nf = 0; nf < NF; nf++) {
                int r0 = m0 + wm + mf * 16 + row;
                int cc = n0 + wn + nf * 8 + colp;
                *(float2*)(out + (size_t)r0 * ldc + cc) =
                    make_float2(acc[mf][nf][0], acc[mf][nf][1]);
                *(float2*)(out + (size_t)(r0 + 8) * ldc + cc) =
                    make_float2(acc[mf][nf][2], acc[mf][nf][3]);
            }
        }
    } else if (MODE == 1) {
        // + P[h] + P[t] + E1 + E2, ReLU, bf16 hi/lo -> g_hhi / g_hlo
        #pragma unroll
        for (int mf = 0; mf < 2; mf++) {
            #pragma unroll
            for (int rr = 0; rr < 2; rr++) {
                int r = m0 + wm + mf * 16 + row + rr * 8;
                int b = r / Rx;
                int hrow = b * Vx + hti[r * 2 + 0];
                int trow = b * Vx + hti[r * 2 + 1];
                const float* ph = g_P + (size_t)hrow * 768;
                const float* pt = g_P + (size_t)trow * 768 + HIDx;
                const float* e1 = g_e1 + dht[r] * HIDx;
                const float* e2 = g_e2 + dth[r] * HIDx;
                #pragma unroll
                for (int nf = 0; nf < NF; nf++) {
                    int cc = n0 + wn + nf * 8 + colp;
                    float2 a0 = *(const float2*)(ph + cc);
                    float2 a1 = *(const float2*)(pt + cc);
                    float2 a2 = *(const float2*)(e1 + cc);
                    float2 a3 = *(const float2*)(e2 + cc);
                    float v0 = fmaxf(acc[mf][nf][rr * 2 + 0] + a0.x + a1.x + a2.x + a3.x, 0.f);
                    float v1 = fmaxf(acc[mf][nf][rr * 2 + 1] + a0.y + a1.y + a2.y + a3.y, 0.f);
                    __nv_bfloat162 h, l;
                    split2(v0, v1, &h, &l);
                    size_t o = ((size_t)r * HIDx + cc) / 2;
                    ((__nv_bfloat162*)g_hhi)[o] = h;
                    ((__nv_bfloat162*)g_hlo)[o] = l;
                }
            }
        }
    } else {
        // + bias, guard n < RELx, fp32 -> out
        #pragma unroll
        for (int mf = 0; mf < 2; mf++) {
            #pragma unroll
            for (int rr = 0; rr < 2; rr++) {
                int r = m0 + wm + mf * 16 + row + rr * 8;
                #pragma unroll
                for (int nf = 0; nf < NF; nf++) {
                    int cc = n0 + wn + nf * 8 + colp;
                    if (cc < RELx)
                        out[(size_t)r * RELx + cc] =
                            acc[mf][nf][rr * 2 + 0] + bias[cc];
                    if (cc + 1 < RELx)
                        out[(size_t)r * RELx + cc + 1] =
                            acc[mf][nf][rr * 2 + 1] + bias[cc + 1];
                }
            }
        }
    }
}

#define SMEM_NF4 (2 * (2 * 128 * PAD * 2 + 2 * 64 * PAD * 2))   // 61440
#define SMEM_NF2 (2 * (2 * 128 * PAD * 2 + 2 * 32 * PAD * 2))   // 51200

// ---------------------------------------------------------------------------
// Launch
// ---------------------------------------------------------------------------
extern "C" void kernel_launch(void* const* d_in, const int* in_sizes, int n_in,
                              void* d_out, int out_size) {
    const float* sent  = (const float*)d_in[0];
    const int*   spans = (const int*)d_in[1];
    const int*   vidx  = (const int*)d_in[3];
    const int*   vmask = (const int*)d_in[4];
    const int*   hti   = (const int*)d_in[5];
    const int*   dht   = (const int*)d_in[7];
    const int*   dth   = (const int*)d_in[8];
    const float* dis   = (const float*)d_in[9];
    const float* W1    = (const float*)d_in[10];
    const float* W2    = (const float*)d_in[11];
    const float* b2    = (const float*)d_in[12];
    float* out = (float*)d_out;

    cudaFuncSetAttribute(gemm_hilo<2, 0>,
                         cudaFuncAttributeMaxDynamicSharedMemorySize, SMEM_NF2);
    cudaFuncSetAttribute(gemm_hilo<4, 1>,
                         cudaFuncAttributeMaxDynamicSharedMemorySize, SMEM_NF4);
    cudaFuncSetAttribute(gemm_hilo<4, 2>,
                         cudaFuncAttributeMaxDynamicSharedMemorySize, SMEM_NF4);

    span_kernel<<<Bx * NSx, 192>>>(sent, spans);
    vertex_kernel<<<NVERT, 192>>>(vidx, vmask);
    feat_prod<<<MROWS, 192>>>(hti);
    prep_w<<<1152, 256>>>(W1);
    prep_w2<<<128, 256>>>(W2);
    e_table<<<dim3(20, 2), HIDx>>>(dis, W1);

    __nv_bfloat16 *p_vhi, *p_vlo, *p_phi, *p_plo;
    __nv_bfloat16 *p_bvhi, *p_bvlo, *p_bphi, *p_bplo;
    __nv_bfloat16 *p_hhi, *p_hlo, *p_w2hi, *p_w2lo;
    float *p_P;
    cudaGetSymbolAddress((void**)&p_vhi,  g_vhi);
    cudaGetSymbolAddress((void**)&p_vlo,  g_vlo);
    cudaGetSymbolAddress((void**)&p_phi,  g_phi);
    cudaGetSymbolAddress((void**)&p_plo,  g_plo);
    cudaGetSymbolAddress((void**)&p_bvhi, g_bvhi);
    cudaGetSymbolAddress((void**)&p_bvlo, g_bvlo);
    cudaGetSymbolAddress((void**)&p_bphi, g_bphi);
    cudaGetSymbolAddress((void**)&p_bplo, g_bplo);
    cudaGetSymbolAddress((void**)&p_hhi,  g_hhi);
    cudaGetSymbolAddress((void**)&p_hlo,  g_hlo);
    cudaGetSymbolAddress((void**)&p_w2hi, g_w2hi);
    cudaGetSymbolAddress((void**)&p_w2lo, g_w2lo);
    cudaGetSymbolAddress((void**)&p_P,    g_P);

    // GEMM_V: P[2048 x 768] = vertex_emb @ [W1a|W1c]   (BN=32 -> 384 CTAs)
    gemm_hilo<2, 0><<<dim3(768 / 32, NVERT / 128), 256, SMEM_NF2>>>(
        p_vhi, p_vlo, p_bvhi, p_bvlo, p_P, 768, KD, KD / BKx,
        nullptr, nullptr, nullptr, nullptr);
    // GEMM_P: hid = relu(prod @ W1e + gathered terms) -> bf16 hi/lo
    gemm_hilo<4, 1><<<dim3(HIDx / 64, MROWS / 128), 256, SMEM_NF4>>>(
        p_phi, p_plo, p_bphi, p_bplo, nullptr, HIDx, KD, KD / BKx,
        hti, dht, dth, nullptr);
    // GEMM2: out = hid @ W2 + b2   (N padded 97 -> 128)
    gemm_hilo<4, 2><<<dim3(128 / 64, MROWS / 128), 256, SMEM_NF4>>>(
        p_hhi, p_hlo, p_w2hi, p_w2lo, out, RELx, HIDx, HIDx / BKx,
        nullptr, nullptr, nullptr, b2);
}

// round 11
// speedup vs baseline: 5.3844x; 1.7651x over previous
#include <cuda_runtime.h>
#include <cuda_fp16.h>
#include <cstdint>

// Problem constants
#define Bx    16
#define Sx    1024
#define Dx    768
#define NSx   256
#define Vx    128
#define Cx    6
#define Rx    512
#define RELx  97
#define HIDx  384
#define DISx  20
#define FINx  (Dx + DISx)          // 788
#define KF    (2 * FINx + Dx)      // 2344
#define MROWS (Bx * Rx)            // 8192
#define NVERT (Bx * Vx)            // 2048
#define KD    768
#define BKx   32

// W1 row-block offsets: [head 0..767 | eh 768..787 | tail 788..1555 |
//                        et 1556..1575 | prod 1576..2343]
#define W1_EH   768
#define W1_TAIL 788
#define W1_ET   1556
#define W1_PROD 1576

// Scratch (static device globals — no allocation allowed)
__device__ float g_span[(size_t)Bx * NSx * Dx];
__device__ float g_vert[(size_t)NVERT * Dx];
__device__ __align__(16) __half g_vh[(size_t)NVERT * KD];    // vertex fp16
__device__ __align__(16) __half g_ph[(size_t)MROWS * KD];    // head*tail fp16
__device__ __align__(16) __half g_bv[(size_t)768 * KD];      // [W1a|W1c]^T
__device__ __align__(16) __half g_bp[(size_t)HIDx * KD];     // W1e^T
__device__ __align__(16) __half g_hh[(size_t)MROWS * HIDx];  // hid fp16
__device__ __align__(16) __half g_w2h[(size_t)128 * HIDx];   // W2^T padded
__device__ float g_P[(size_t)NVERT * 768];                   // vertex proj
__device__ float g_e1[20 * HIDx];
__device__ float g_e2[20 * HIDx];

// ---------------------------------------------------------------------------
// PTX helpers (sm_80-era only — tcgen05 won't assemble for compute_103)
// ---------------------------------------------------------------------------
__device__ __forceinline__ uint32_t smem_u32(const void* p) {
    uint32_t a;
    asm("{ .reg .u64 t; cvta.to.shared.u64 t, %1; cvt.u32.u64 %0, t; }"
        : "=r"(a) : "l"(p));
    return a;
}

__device__ __forceinline__ void ldsm4(uint32_t* r, uint32_t addr) {
    asm volatile("ldmatrix.sync.aligned.m8n8.x4.shared.b16 {%0,%1,%2,%3}, [%4];"
                 : "=r"(r[0]), "=r"(r[1]), "=r"(r[2]), "=r"(r[3]) : "r"(addr));
}

__device__ __forceinline__ void mma_fp16(float* d, const uint32_t* a,
                                         uint32_t b0, uint32_t b1) {
    asm volatile(
        "mma.sync.aligned.m16n8k16.row.col.f32.f16.f16.f32 "
        "{%0,%1,%2,%3}, {%4,%5,%6,%7}, {%8,%9}, {%0,%1,%2,%3};"
        : "+f"(d[0]), "+f"(d[1]), "+f"(d[2]), "+f"(d[3])
        : "r"(a[0]), "r"(a[1]), "r"(a[2]), "r"(a[3]), "r"(b0), "r"(b1));
}

__device__ __forceinline__ void cp16(uint32_t dst, const void* src) {
    asm volatile("cp.async.cg.shared.global [%0], [%1], 16;"
                 :: "r"(dst), "l"(src));
}
#define CP_COMMIT() asm volatile("cp.async.commit_group;" ::: "memory")
#define CP_WAIT(n)  asm volatile("cp.async.wait_group %0;" :: "n"(n) : "memory")

// ---------------------------------------------------------------------------
// Stage 1: span max-pool
// ---------------------------------------------------------------------------
__global__ void span_kernel(const float* __restrict__ sent,
                            const int* __restrict__ spans) {
    int bs = blockIdx.x;
    int b  = bs / NSx;
    int start = spans[bs * 2 + 0];
    int end   = spans[bs * 2 + 1];
    int w = end - start;
    const float4* base = (const float4*)(sent + ((size_t)b * Sx + start) * Dx);
    int t = threadIdx.x;
    float4 m = base[t];
    for (int j = 1; j <= w; j++) {
        float4 v = base[(size_t)j * (Dx / 4) + t];
        m.x = fmaxf(m.x, v.x); m.y = fmaxf(m.y, v.y);
        m.z = fmaxf(m.z, v.z); m.w = fmaxf(m.w, v.w);
    }
    ((float4*)(g_span + (size_t)bs * Dx))[t] = m;
}

// ---------------------------------------------------------------------------
// Stage 2: vertex masked mean (fp32 + fp16 for GEMM_V)
// ---------------------------------------------------------------------------
__global__ void vertex_kernel(const int* __restrict__ vidx,
                              const int* __restrict__ vmask) {
    int bv = blockIdx.x;
    int b  = bv / Vx;
    int t  = threadIdx.x;             // 0..191
    float4 acc = make_float4(0.f, 0.f, 0.f, 0.f);
    float cnt = 0.f;
    #pragma unroll
    for (int c = 0; c < Cx; c++) {
        int mk = vmask[bv * Cx + c];
        if (mk) {
            int idx = vidx[bv * Cx + c];
            float4 v = ((const float4*)(g_span + ((size_t)b * NSx + idx) * Dx))[t];
            acc.x += v.x; acc.y += v.y; acc.z += v.z; acc.w += v.w;
            cnt += 1.f;
        }
    }
    float inv = 1.f / fmaxf(cnt, 1.f);
    acc.x *= inv; acc.y *= inv; acc.z *= inv; acc.w *= inv;
    ((float4*)(g_vert + (size_t)bv * Dx))[t] = acc;

    size_t o2 = (size_t)bv * (KD / 2) + t * 2;
    ((__half2*)g_vh)[o2]     = __floats2half2_rn(acc.x, acc.y);
    ((__half2*)g_vh)[o2 + 1] = __floats2half2_rn(acc.z, acc.w);
}

// ---------------------------------------------------------------------------
// Stage 3: product features  head∘tail -> fp16  (8192 x 768)
// ---------------------------------------------------------------------------
__global__ void feat_prod(const int* __restrict__ hti) {
    int m = blockIdx.x;
    int b = m / Rx;
    int h  = hti[m * 2 + 0];
    int tl = hti[m * 2 + 1];
    const float4* hp = (const float4*)(g_vert + ((size_t)b * Vx + h)  * Dx);
    const float4* tp = (const float4*)(g_vert + ((size_t)b * Vx + tl) * Dx);
    int t = threadIdx.x;              // 0..191
    float4 a = hp[t], c = tp[t];
    size_t o2 = (size_t)m * (KD / 2) + t * 2;
    ((__half2*)g_ph)[o2]     = __floats2half2_rn(a.x * c.x, a.y * c.y);
    ((__half2*)g_ph)[o2 + 1] = __floats2half2_rn(a.z * c.z, a.w * c.w);
}

// ---------------------------------------------------------------------------
// Stage 3b: merged weight prep (coalesced tile transpose) + distance tables.
//   blocks [0,576):    Bv[768 x 768]  = [W1a | W1c]^T
//   blocks [576,864):  Bp[384 x 768]  = W1e^T
//   blocks [864,912):  W2t[128 x 384] = W2^T (padded rows >= 97 are zero)
//   blocks [912,952):  E1/E2[20 x 384] fp32 (exact)
// 256 threads; transpose via 32x33 fp32 smem tile.
// ---------------------------------------------------------------------------
__global__ void prep_all(const float* __restrict__ W1,
                         const float* __restrict__ W2,
                         const float* __restrict__ dis) {
    __shared__ float tile[32][33];
    int idx = blockIdx.x;
    int t  = threadIdx.x;
    int tx = t & 31, ty = t >> 5;       // 32 x 8

    if (idx < 912) {
        int k0, n0;
        const float* src;
        int src_ld, src_guard;
        __half* dst;
        if (idx < 576) {                // Bv: 24 k-tiles x 24 n-tiles
            int kt = idx / 24, nt = idx % 24;
            k0 = kt * 32; n0 = nt * 32;
            if (n0 < 384) { src = W1 + (size_t)k0 * HIDx + n0; }
            else          { src = W1 + (size_t)(W1_TAIL + k0) * HIDx + (n0 - 384); }
            src_ld = HIDx; src_guard = 32;
            dst = g_bv + (size_t)n0 * KD + k0;
        } else if (idx < 864) {         // Bp: 24 k-tiles x 12 n-tiles
            int q = idx - 576;
            int kt = q / 12, nt = q % 12;
            k0 = kt * 32; n0 = nt * 32;
            src = W1 + (size_t)(W1_PROD + k0) * HIDx + n0;
            src_ld = HIDx; src_guard = 32;
            dst = g_bp + (size_t)n0 * KD + k0;
        } else {                        // W2t: 12 k-tiles x 4 n-tiles
            int q = idx - 864;
            int kt = q / 4, nt = q % 4;
            k0 = kt * 32; n0 = nt * 32;
            src = W2 + (size_t)k0 * RELx + n0;
            src_ld = RELx;
            src_guard = (n0 + 32 <= RELx) ? 32 : (RELx > n0 ? RELx - n0 : 0);
            dst = g_w2h + (size_t)n0 * HIDx + k0;
        }
        // read [32k x 32n] coalesced
        #pragma unroll
        for (int i = 0; i < 4; i++) {
            int r = i * 8 + ty;
            tile[r][tx] = (tx < src_guard) ? src[(size_t)r * src_ld + tx] : 0.f;
        }
        __syncthreads();
        // write transposed: row = n, col = k (k contiguous)
        int KOUT = (idx < 864) ? KD : HIDx;
        #pragma unroll
        for (int i = 0; i < 4; i++) {
            int r = i * 8 + ty;         // n within tile
            dst[(size_t)r * KOUT + tx] = __float2half(tile[tx][r]);
        }
    } else {                            // distance tables
        int q = idx - 912;
        int d = q % 20, which = q / 20;
        int wbase = which ? W1_ET : W1_EH;
        float* outp = which ? g_e2 : g_e1;
        for (int n = t; n < HIDx; n += 256) {
            float s = 0.f;
            #pragma unroll
            for (int j = 0; j < DISx; j++)
                s += dis[d * DISx + j] * W1[(size_t)(wbase + j) * HIDx + n];
            outp[d * HIDx + n] = s;
        }
    }
}

// ---------------------------------------------------------------------------
// Single-stream fp16 HMMA GEMM: out[M x N] = A[M x K] * B[N x K]^T, fp32 accum
//   BM=128, BN=NF*16; 8 warps (4m x 2n); 3 CTAs/SM.
//   MODE 0: plain fp32 store (GEMM_V -> P)
//   MODE 1: + gathered P/E1/E2 terms, ReLU, fp16 store (GEMM_P -> hid)
//   MODE 2: + bias, n<RELx guard, fp32 store (GEMM2 -> out)
// ---------------------------------------------------------------------------
#define PAD 40                          // fp16 elems per smem row (80B stride)

template <int NF, int MODE>
__global__ __launch_bounds__(256, 3) void gemm_fp16(
    const __half* __restrict__ A, const __half* __restrict__ B,
    float* __restrict__ out, int ldc, int K, int nch,
    const int* __restrict__ hti, const int* __restrict__ dht,
    const int* __restrict__ dth, const float* __restrict__ bias) {
    constexpr int BN    = NF * 16;
    constexpr int ARR_A = 128 * PAD * 2;
    constexpr int ARR_B = BN * PAD * 2;
    constexpr int STG   = ARR_A + ARR_B;

    extern __shared__ char smem[];
    uint32_t sb = smem_u32(smem);
    int t = threadIdx.x, wid = t >> 5, lane = t & 31;
    int n0 = blockIdx.x * BN;
    int m0 = blockIdx.y * 128;
    int wm = (wid & 3) * 32;
    int wn = (wid >> 2) * (NF * 8);

    float acc[2][NF][4];
    #pragma unroll
    for (int i = 0; i < 2; i++)
        #pragma unroll
        for (int j = 0; j < NF; j++)
            #pragma unroll
            for (int q = 0; q < 4; q++) acc[i][j][q] = 0.f;

    auto load_chunk = [&](int k0, int s) {
        uint32_t stg = sb + (uint32_t)s * STG;
        #pragma unroll
        for (int i = 0; i < 2; i++) {               // A: 512 16B chunks
            int e = (i << 8) + t;
            int r = e >> 2;
            int c = e & 3;
            cp16(stg + r * (PAD * 2) + c * 16,
                 A + (size_t)(m0 + r) * K + k0 + c * 8);
        }
        if (t < BN * 4) {                           // B: BN*4 chunks
            int r = t >> 2, c = t & 3;
            cp16(stg + ARR_A + r * (PAD * 2) + c * 16,
                 B + (size_t)(n0 + r) * K + k0 + c * 8);
        }
    };

    load_chunk(0, 0);
    CP_COMMIT();

    int lr = lane & 15;
    int lc = lane >> 4;

    for (int c = 0; c < nch; c++) {
        int s = c & 1;
        if (c + 1 < nch) {
            load_chunk((c + 1) * BKx, s ^ 1);
            CP_COMMIT();
            CP_WAIT(1);
        } else {
            CP_WAIT(0);
        }
        __syncthreads();

        uint32_t a_base = sb + (uint32_t)s * STG;
        uint32_t b_base = a_base + ARR_A;

        #pragma unroll
        for (int ks = 0; ks < 2; ks++) {
            uint32_t koff = (uint32_t)(ks * 16 + lc * 8) * 2;
            uint32_t af[2][4];
            #pragma unroll
            for (int mf = 0; mf < 2; mf++) {
                uint32_t ro = (uint32_t)(wm + mf * 16 + lr) * (PAD * 2) + koff;
                ldsm4(af[mf], a_base + ro);
            }
            uint32_t bf[NF * 2];
            #pragma unroll
            for (int g = 0; g < NF / 2; g++) {
                uint32_t ro = (uint32_t)(wn + g * 16 + lr) * (PAD * 2) + koff;
                ldsm4(&bf[g * 4], b_base + ro);
            }
            #pragma unroll
            for (int mf = 0; mf < 2; mf++) {
                #pragma unroll
                for (int nf = 0; nf < NF; nf++) {
                    int bi = (nf >> 1) * 4 + (nf & 1);
                    mma_fp16(acc[mf][nf], af[mf], bf[bi], bf[bi + 2]);
                }
            }
        }
        __syncthreads();
    }

    int row  = lane >> 2;
    int colp = (lane & 3) * 2;
    if (MODE == 0) {
        #pragma unroll
        for (int mf = 0; mf < 2; mf++) {
            #pragma unroll
            for (int nf = 0; nf < NF; nf++) {
                int r0 = m0 + wm + mf * 16 + row;
                int cc = n0 + wn + nf * 8 + colp;
                *(float2*)(out + (size_t)r0 * ldc + cc) =
                    make_float2(acc[mf][nf][0], acc[mf][nf][1]);
                *(float2*)(out + (size_t)(r0 + 8) * ldc + cc) =
                    make_float2(acc[mf][nf][2], acc[mf][nf][3]);
            }
        }
    } else if (MODE == 1) {
        // + P[h] + P[t] + E1 + E2, ReLU, fp16 -> g_hh
        #pragma unroll
        for (int mf = 0; mf < 2; mf++) {
            #pragma unroll
            for (int rr = 0; rr < 2; rr++) {
                int r = m0 + wm + mf * 16 + row + rr * 8;
                int b = r / Rx;
                int hrow = b * Vx + hti[r * 2 + 0];
                int trow = b * Vx + hti[r * 2 + 1];
                const float* ph = g_P + (size_t)hrow * 768;
                const float* pt = g_P + (size_t)trow * 768 + HIDx;
                const float* e1 = g_e1 + dht[r] * HIDx;
                const float* e2 = g_e2 + dth[r] * HIDx;
                #pragma unroll
                for (int nf = 0; nf < NF; nf++) {
                    int cc = n0 + wn + nf * 8 + colp;
                    float2 a0 = *(const float2*)(ph + cc);
                    float2 a1 = *(const float2*)(pt + cc);
                    float2 a2 = *(const float2*)(e1 + cc);
                    float2 a3 = *(const float2*)(e2 + cc);
                    float v0 = fmaxf(acc[mf][nf][rr * 2 + 0] + a0.x + a1.x + a2.x + a3.x, 0.f);
                    float v1 = fmaxf(acc[mf][nf][rr * 2 + 1] + a0.y + a1.y + a2.y + a3.y, 0.f);
                    ((__half2*)g_hh)[((size_t)r * HIDx + cc) / 2] =
                        __floats2half2_rn(v0, v1);
                }
            }
        }
    } else {
        // + bias, guard n < RELx, fp32 -> out
        #pragma unroll
        for (int mf = 0; mf < 2; mf++) {
            #pragma unroll
            for (int rr = 0; rr < 2; rr++) {
                int r = m0 + wm + mf * 16 + row + rr * 8;
                #pragma unroll
                for (int nf = 0; nf < NF; nf++) {
                    int cc = n0 + wn + nf * 8 + colp;
                    if (cc < RELx)
                        out[(size_t)r * RELx + cc] =
                            acc[mf][nf][rr * 2 + 0] + bias[cc];
                    if (cc + 1 < RELx)
                        out[(size_t)r * RELx + cc + 1] =
                            acc[mf][nf][rr * 2 + 1] + bias[cc + 1];
                }
            }
        }
    }
}

#define SMEM_NF4 (2 * (128 * PAD * 2 + 64 * PAD * 2))   // 30720
#define SMEM_NF2 (2 * (128 * PAD * 2 + 32 * PAD * 2))   // 25600

// ---------------------------------------------------------------------------
// Launch
// ---------------------------------------------------------------------------
extern "C" void kernel_launch(void* const* d_in, const int* in_sizes, int n_in,
                              void* d_out, int out_size) {
    const float* sent  = (const float*)d_in[0];
    const int*   spans = (const int*)d_in[1];
    const int*   vidx  = (const int*)d_in[3];
    const int*   vmask = (const int*)d_in[4];
    const int*   hti   = (const int*)d_in[5];
    const int*   dht   = (const int*)d_in[7];
    const int*   dth   = (const int*)d_in[8];
    const float* dis   = (const float*)d_in[9];
    const float* W1    = (const float*)d_in[10];
    const float* W2    = (const float*)d_in[11];
    const float* b2    = (const float*)d_in[12];
    float* out = (float*)d_out;

    cudaFuncSetAttribute(gemm_fp16<2, 0>,
                         cudaFuncAttributeMaxDynamicSharedMemorySize, SMEM_NF2);
    cudaFuncSetAttribute(gemm_fp16<4, 1>,
                         cudaFuncAttributeMaxDynamicSharedMemorySize, SMEM_NF4);
    cudaFuncSetAttribute(gemm_fp16<4, 2>,
                         cudaFuncAttributeMaxDynamicSharedMemorySize, SMEM_NF4);

    span_kernel<<<Bx * NSx, 192>>>(sent, spans);
    vertex_kernel<<<NVERT, 192>>>(vidx, vmask);
    feat_prod<<<MROWS, 192>>>(hti);
    prep_all<<<952, 256>>>(W1, W2, dis);

    __half *p_vh, *p_ph, *p_bv, *p_bp, *p_hh, *p_w2h;
    float *p_P;
    cudaGetSymbolAddress((void**)&p_vh,  g_vh);
    cudaGetSymbolAddress((void**)&p_ph,  g_ph);
    cudaGetSymbolAddress((void**)&p_bv,  g_bv);
    cudaGetSymbolAddress((void**)&p_bp,  g_bp);
    cudaGetSymbolAddress((void**)&p_hh,  g_hh);
    cudaGetSymbolAddress((void**)&p_w2h, g_w2h);
    cudaGetSymbolAddress((void**)&p_P,   g_P);

    // GEMM_V: P[2048 x 768] = vertex_emb @ [W1a|W1c]   (BN=32 -> 384 CTAs)
    gemm_fp16<2, 0><<<dim3(768 / 32, NVERT / 128), 256, SMEM_NF2>>>(
        p_vh, p_bv, p_P, 768, KD, KD / BKx, nullptr, nullptr, nullptr, nullptr);
    // GEMM_P: hid = relu(prod @ W1e + gathered terms) -> fp16
    gemm_fp16<4, 1><<<dim3(HIDx / 64, MROWS / 128), 256, SMEM_NF4>>>(
        p_ph, p_bp, nullptr, HIDx, KD, KD / BKx, hti, dht, dth, nullptr);
    // GEMM2: out = hid @ W2 + b2   (N padded 97 -> 128)
    gemm_fp16<4, 2><<<dim3(128 / 64, MROWS / 128), 256, SMEM_NF4>>>(
        p_hh, p_w2h, out, RELx, HIDx, HIDx / BKx, nullptr, nullptr, nullptr, b2);
}

// round 12
// speedup vs baseline: 5.6308x; 1.0457x over previous
#include <cuda_runtime.h>
#include <cuda_fp16.h>
#include <cstdint>

// Problem constants
#define Bx    16
#define Sx    1024
#define Dx    768
#define NSx   256
#define Vx    128
#define Cx    6
#define Rx    512
#define RELx  97
#define HIDx  384
#define DISx  20
#define FINx  (Dx + DISx)          // 788
#define KF    (2 * FINx + Dx)      // 2344
#define MROWS (Bx * Rx)            // 8192
#define NVERT (Bx * Vx)            // 2048
#define KD    768
#define BKx   32

// W1 row-block offsets: [head 0..767 | eh 768..787 | tail 788..1555 |
//                        et 1556..1575 | prod 1576..2343]
#define W1_EH   768
#define W1_TAIL 788
#define W1_ET   1556
#define W1_PROD 1576

// Scratch (static device globals — no allocation allowed)
__device__ float g_span[(size_t)Bx * NSx * Dx];
__device__ float g_vert[(size_t)NVERT * Dx];
__device__ __align__(16) __half g_vh[(size_t)NVERT * KD];    // vertex fp16
__device__ __align__(16) __half g_ph[(size_t)MROWS * KD];    // head*tail fp16
__device__ __align__(16) __half g_bv[(size_t)768 * KD];      // [W1a|W1c]^T
__device__ __align__(16) __half g_bp[(size_t)HIDx * KD];     // W1e^T
__device__ __align__(16) __half g_hh[(size_t)MROWS * HIDx];  // hid fp16
__device__ __align__(16) __half g_w2h[(size_t)128 * HIDx];   // W2^T padded
__device__ float g_P[(size_t)NVERT * 768];                   // vertex proj
__device__ float g_e1[20 * HIDx];
__device__ float g_e2[20 * HIDx];

// ---------------------------------------------------------------------------
// PTX helpers (sm_80-era only — tcgen05 won't assemble for compute_103)
// ---------------------------------------------------------------------------
__device__ __forceinline__ uint32_t smem_u32(const void* p) {
    uint32_t a;
    asm("{ .reg .u64 t; cvta.to.shared.u64 t, %1; cvt.u32.u64 %0, t; }"
        : "=r"(a) : "l"(p));
    return a;
}

__device__ __forceinline__ void ldsm4(uint32_t* r, uint32_t addr) {
    asm volatile("ldmatrix.sync.aligned.m8n8.x4.shared.b16 {%0,%1,%2,%3}, [%4];"
                 : "=r"(r[0]), "=r"(r[1]), "=r"(r[2]), "=r"(r[3]) : "r"(addr));
}

__device__ __forceinline__ void mma_fp16(float* d, const uint32_t* a,
                                         uint32_t b0, uint32_t b1) {
    asm volatile(
        "mma.sync.aligned.m16n8k16.row.col.f32.f16.f16.f32 "
        "{%0,%1,%2,%3}, {%4,%5,%6,%7}, {%8,%9}, {%0,%1,%2,%3};"
        : "+f"(d[0]), "+f"(d[1]), "+f"(d[2]), "+f"(d[3])
        : "r"(a[0]), "r"(a[1]), "r"(a[2]), "r"(a[3]), "r"(b0), "r"(b1));
}

__device__ __forceinline__ void cp16(uint32_t dst, const void* src) {
    asm volatile("cp.async.cg.shared.global [%0], [%1], 16;"
                 :: "r"(dst), "l"(src));
}
#define CP_COMMIT() asm volatile("cp.async.commit_group;" ::: "memory")
#define CP_WAIT(n)  asm volatile("cp.async.wait_group %0;" :: "n"(n) : "memory")

// ---------------------------------------------------------------------------
// Stage 1: span max-pool
// ---------------------------------------------------------------------------
__global__ void span_kernel(const float* __restrict__ sent,
                            const int* __restrict__ spans) {
    int bs = blockIdx.x;
    int b  = bs / NSx;
    int start = spans[bs * 2 + 0];
    int end   = spans[bs * 2 + 1];
    int w = end - start;
    const float4* base = (const float4*)(sent + ((size_t)b * Sx + start) * Dx);
    int t = threadIdx.x;
    float4 m = base[t];
    for (int j = 1; j <= w; j++) {
        float4 v = base[(size_t)j * (Dx / 4) + t];
        m.x = fmaxf(m.x, v.x); m.y = fmaxf(m.y, v.y);
        m.z = fmaxf(m.z, v.z); m.w = fmaxf(m.w, v.w);
    }
    ((float4*)(g_span + (size_t)bs * Dx))[t] = m;
}

// ---------------------------------------------------------------------------
// Stage 2: vertex masked mean (fp32 + fp16 for GEMM_V)
// ---------------------------------------------------------------------------
__global__ void vertex_kernel(const int* __restrict__ vidx,
                              const int* __restrict__ vmask) {
    int bv = blockIdx.x;
    int b  = bv / Vx;
    int t  = threadIdx.x;             // 0..191
    float4 acc = make_float4(0.f, 0.f, 0.f, 0.f);
    float cnt = 0.f;
    #pragma unroll
    for (int c = 0; c < Cx; c++) {
        int mk = vmask[bv * Cx + c];
        if (mk) {
            int idx = vidx[bv * Cx + c];
            float4 v = ((const float4*)(g_span + ((size_t)b * NSx + idx) * Dx))[t];
            acc.x += v.x; acc.y += v.y; acc.z += v.z; acc.w += v.w;
            cnt += 1.f;
        }
    }
    float inv = 1.f / fmaxf(cnt, 1.f);
    acc.x *= inv; acc.y *= inv; acc.z *= inv; acc.w *= inv;
    ((float4*)(g_vert + (size_t)bv * Dx))[t] = acc;

    size_t o2 = (size_t)bv * (KD / 2) + t * 2;
    ((__half2*)g_vh)[o2]     = __floats2half2_rn(acc.x, acc.y);
    ((__half2*)g_vh)[o2 + 1] = __floats2half2_rn(acc.z, acc.w);
}

// ---------------------------------------------------------------------------
// Stage 3: product features  head∘tail -> fp16  (8192 x 768)
// ---------------------------------------------------------------------------
__global__ void feat_prod(const int* __restrict__ hti) {
    int m = blockIdx.x;
    int b = m / Rx;
    int h  = hti[m * 2 + 0];
    int tl = hti[m * 2 + 1];
    const float4* hp = (const float4*)(g_vert + ((size_t)b * Vx + h)  * Dx);
    const float4* tp = (const float4*)(g_vert + ((size_t)b * Vx + tl) * Dx);
    int t = threadIdx.x;              // 0..191
    float4 a = hp[t], c = tp[t];
    size_t o2 = (size_t)m * (KD / 2) + t * 2;
    ((__half2*)g_ph)[o2]     = __floats2half2_rn(a.x * c.x, a.y * c.y);
    ((__half2*)g_ph)[o2 + 1] = __floats2half2_rn(a.z * c.z, a.w * c.w);
}

// ---------------------------------------------------------------------------
// Stage 3b: merged weight prep (coalesced tile transpose) + distance tables.
//   blocks [0,576):    Bv[768 x 768]  = [W1a | W1c]^T
//   blocks [576,864):  Bp[384 x 768]  = W1e^T
//   blocks [864,912):  W2t[128 x 384] = W2^T (padded rows >= 97 are zero)
//   blocks [912,952):  E1/E2[20 x 384] fp32 (exact)
// ---------------------------------------------------------------------------
__global__ void prep_all(const float* __restrict__ W1,
                         const float* __restrict__ W2,
                         const float* __restrict__ dis) {
    __shared__ float tile[32][33];
    int idx = blockIdx.x;
    int t  = threadIdx.x;
    int tx = t & 31, ty = t >> 5;       // 32 x 8

    if (idx < 912) {
        int k0, n0;
        const float* src;
        int src_ld, src_guard;
        __half* dst;
        if (idx < 576) {                // Bv: 24 k-tiles x 24 n-tiles
            int kt = idx / 24, nt = idx % 24;
            k0 = kt * 32; n0 = nt * 32;
            if (n0 < 384) { src = W1 + (size_t)k0 * HIDx + n0; }
            else          { src = W1 + (size_t)(W1_TAIL + k0) * HIDx + (n0 - 384); }
            src_ld = HIDx; src_guard = 32;
            dst = g_bv + (size_t)n0 * KD + k0;
        } else if (idx < 864) {         // Bp: 24 k-tiles x 12 n-tiles
            int q = idx - 576;
            int kt = q / 12, nt = q % 12;
            k0 = kt * 32; n0 = nt * 32;
            src = W1 + (size_t)(W1_PROD + k0) * HIDx + n0;
            src_ld = HIDx; src_guard = 32;
            dst = g_bp + (size_t)n0 * KD + k0;
        } else {                        // W2t: 12 k-tiles x 4 n-tiles
            int q = idx - 864;
            int kt = q / 4, nt = q % 4;
            k0 = kt * 32; n0 = nt * 32;
            src = W2 + (size_t)k0 * RELx + n0;
            src_ld = RELx;
            src_guard = (n0 + 32 <= RELx) ? 32 : (RELx > n0 ? RELx - n0 : 0);
            dst = g_w2h + (size_t)n0 * HIDx + k0;
        }
        #pragma unroll
        for (int i = 0; i < 4; i++) {
            int r = i * 8 + ty;
            tile[r][tx] = (tx < src_guard) ? src[(size_t)r * src_ld + tx] : 0.f;
        }
        __syncthreads();
        int KOUT = (idx < 864) ? KD : HIDx;
        #pragma unroll
        for (int i = 0; i < 4; i++) {
            int r = i * 8 + ty;         // n within tile
            dst[(size_t)r * KOUT + tx] = __float2half(tile[tx][r]);
        }
    } else {                            // distance tables
        int q = idx - 912;
        int d = q % 20, which = q / 20;
        int wbase = which ? W1_ET : W1_EH;
        float* outp = which ? g_e2 : g_e1;
        for (int n = t; n < HIDx; n += 256) {
            float s = 0.f;
            #pragma unroll
            for (int j = 0; j < DISx; j++)
                s += dis[d * DISx + j] * W1[(size_t)(wbase + j) * HIDx + n];
            outp[d * HIDx + n] = s;
        }
    }
}

// ---------------------------------------------------------------------------
// Single-stream fp16 HMMA GEMM: out[M x N] = A[M x K] * B[N x K]^T, fp32 accum
//   BM=128, BN=NF*16; 8 warps (4m x 2n); 3 CTAs/SM.
//   MODE 0: plain fp32 store (GEMM_V -> P)
//   MODE 1: + gathered P/E1/E2 terms, ReLU, fp16 store (GEMM_P -> hid)
//   MODE 2: + bias, n<RELx guard, fp32 store (GEMM2 -> out)
// ---------------------------------------------------------------------------
#define PAD 40                          // fp16 elems per smem row (80B stride)

template <int NF, int MODE>
__global__ __launch_bounds__(256, 3) void gemm_fp16(
    const __half* __restrict__ A, const __half* __restrict__ B,
    float* __restrict__ out, int ldc, int K, int nch,
    const int* __restrict__ hti, const int* __restrict__ dht,
    const int* __restrict__ dth, const float* __restrict__ bias) {
    constexpr int BN    = NF * 16;
    constexpr int ARR_A = 128 * PAD * 2;
    constexpr int ARR_B = BN * PAD * 2;
    constexpr int STG   = ARR_A + ARR_B;

    extern __shared__ char smem[];
    uint32_t sb = smem_u32(smem);
    int t = threadIdx.x, wid = t >> 5, lane = t & 31;
    int n0 = blockIdx.x * BN;
    int m0 = blockIdx.y * 128;
    int wm = (wid & 3) * 32;
    int wn = (wid >> 2) * (NF * 8);

    float acc[2][NF][4];
    #pragma unroll
    for (int i = 0; i < 2; i++)
        #pragma unroll
        for (int j = 0; j < NF; j++)
            #pragma unroll
            for (int q = 0; q < 4; q++) acc[i][j][q] = 0.f;

    auto load_chunk = [&](int k0, int s) {
        uint32_t stg = sb + (uint32_t)s * STG;
        #pragma unroll
        for (int i = 0; i < 2; i++) {               // A: 512 16B chunks
            int e = (i << 8) + t;
            int r = e >> 2;
            int c = e & 3;
            cp16(stg + r * (PAD * 2) + c * 16,
                 A + (size_t)(m0 + r) * K + k0 + c * 8);
        }
        if (t < BN * 4) {                           // B: BN*4 chunks
            int r = t >> 2, c = t & 3;
            cp16(stg + ARR_A + r * (PAD * 2) + c * 16,
                 B + (size_t)(n0 + r) * K + k0 + c * 8);
        }
    };

    load_chunk(0, 0);
    CP_COMMIT();

    int lr = lane & 15;
    int lc = lane >> 4;

    for (int c = 0; c < nch; c++) {
        int s = c & 1;
        if (c + 1 < nch) {
            load_chunk((c + 1) * BKx, s ^ 1);
            CP_COMMIT();
            CP_WAIT(1);
        } else {
            CP_WAIT(0);
        }
        __syncthreads();

        uint32_t a_base = sb + (uint32_t)s * STG;
        uint32_t b_base = a_base + ARR_A;

        #pragma unroll
        for (int ks = 0; ks < 2; ks++) {
            uint32_t koff = (uint32_t)(ks * 16 + lc * 8) * 2;
            uint32_t af[2][4];
            #pragma unroll
            for (int mf = 0; mf < 2; mf++) {
                uint32_t ro = (uint32_t)(wm + mf * 16 + lr) * (PAD * 2) + koff;
                ldsm4(af[mf], a_base + ro);
            }
            uint32_t bf[NF * 2];
            #pragma unroll
            for (int g = 0; g < NF / 2; g++) {
                uint32_t ro = (uint32_t)(wn + g * 16 + lr) * (PAD * 2) + koff;
                ldsm4(&bf[g * 4], b_base + ro);
            }
            #pragma unroll
            for (int mf = 0; mf < 2; mf++) {
                #pragma unroll
                for (int nf = 0; nf < NF; nf++) {
                    int bi = (nf >> 1) * 4 + (nf & 1);
                    mma_fp16(acc[mf][nf], af[mf], bf[bi], bf[bi + 2]);
                }
            }
        }
        __syncthreads();
    }

    int row  = lane >> 2;
    int colp = (lane & 3) * 2;
    if (MODE == 0) {
        #pragma unroll
        for (int mf = 0; mf < 2; mf++) {
            #pragma unroll
            for (int nf = 0; nf < NF; nf++) {
                int r0 = m0 + wm + mf * 16 + row;
                int cc = n0 + wn + nf * 8 + colp;
                *(float2*)(out + (size_t)r0 * ldc + cc) =
                    make_float2(acc[mf][nf][0], acc[mf][nf][1]);
                *(float2*)(out + (size_t)(r0 + 8) * ldc + cc) =
                    make_float2(acc[mf][nf][2], acc[mf][nf][3]);
            }
        }
    } else if (MODE == 1) {
        // + P[h] + P[t] + E1 + E2, ReLU, fp16 -> g_hh
        #pragma unroll
        for (int mf = 0; mf < 2; mf++) {
            #pragma unroll
            for (int rr = 0; rr < 2; rr++) {
                int r = m0 + wm + mf * 16 + row + rr * 8;
                int b = r / Rx;
                int hrow = b * Vx + hti[r * 2 + 0];
                int trow = b * Vx + hti[r * 2 + 1];
                const float* ph = g_P + (size_t)hrow * 768;
                const float* pt = g_P + (size_t)trow * 768 + HIDx;
                const float* e1 = g_e1 + dht[r] * HIDx;
                const float* e2 = g_e2 + dth[r] * HIDx;
                #pragma unroll
                for (int nf = 0; nf < NF; nf++) {
                    int cc = n0 + wn + nf * 8 + colp;
                    float2 a0 = *(const float2*)(ph + cc);
                    float2 a1 = *(const float2*)(pt + cc);
                    float2 a2 = *(const float2*)(e1 + cc);
                    float2 a3 = *(const float2*)(e2 + cc);
                    float v0 = fmaxf(acc[mf][nf][rr * 2 + 0] + a0.x + a1.x + a2.x + a3.x, 0.f);
                    float v1 = fmaxf(acc[mf][nf][rr * 2 + 1] + a0.y + a1.y + a2.y + a3.y, 0.f);
                    ((__half2*)g_hh)[((size_t)r * HIDx + cc) / 2] =
                        __floats2half2_rn(v0, v1);
                }
            }
        }
    } else {
        // + bias, guard n < RELx, fp32 -> out
        #pragma unroll
        for (int mf = 0; mf < 2; mf++) {
            #pragma unroll
            for (int rr = 0; rr < 2; rr++) {
                int r = m0 + wm + mf * 16 + row + rr * 8;
                #pragma unroll
                for (int nf = 0; nf < NF; nf++) {
                    int cc = n0 + wn + nf * 8 + colp;
                    if (cc < RELx)
                        out[(size_t)r * RELx + cc] =
                            acc[mf][nf][rr * 2 + 0] + bias[cc];
                    if (cc + 1 < RELx)
                        out[(size_t)r * RELx + cc + 1] =
                            acc[mf][nf][rr * 2 + 1] + bias[cc + 1];
                }
            }
        }
    }
}

#define SMEM_NF4 (2 * (128 * PAD * 2 + 64 * PAD * 2))   // 30720
#define SMEM_NF2 (2 * (128 * PAD * 2 + 32 * PAD * 2))   // 25600

// ---------------------------------------------------------------------------
// Launch — fork/join stream DAG (captured as a branching CUDA graph):
//   stream0: span -> vertex -> feat ----------\
//   s1:      prep_all (independent) --- e_prep +--> GEMM_P -> GEMM2
//   s2:      [vertex, prep] -> GEMM_V --- e_gv /
// Streams/events are created lazily on the first (uncaptured) correctness
// call; the capture call reuses them. All branches rejoin stream 0.
// ---------------------------------------------------------------------------
extern "C" void kernel_launch(void* const* d_in, const int* in_sizes, int n_in,
                              void* d_out, int out_size) {
    const float* sent  = (const float*)d_in[0];
    const int*   spans = (const int*)d_in[1];
    const int*   vidx  = (const int*)d_in[3];
    const int*   vmask = (const int*)d_in[4];
    const int*   hti   = (const int*)d_in[5];
    const int*   dht   = (const int*)d_in[7];
    const int*   dth   = (const int*)d_in[8];
    const float* dis   = (const float*)d_in[9];
    const float* W1    = (const float*)d_in[10];
    const float* W2    = (const float*)d_in[11];
    const float* b2    = (const float*)d_in[12];
    float* out = (float*)d_out;

    static cudaStream_t s1 = nullptr, s2 = nullptr;
    static cudaEvent_t e_root = nullptr, e_prep = nullptr, e_vert = nullptr,
                       e_gv = nullptr;
    if (!s1) {
        cudaStreamCreateWithFlags(&s1, cudaStreamNonBlocking);
        cudaStreamCreateWithFlags(&s2, cudaStreamNonBlocking);
        cudaEventCreateWithFlags(&e_root, cudaEventDisableTiming);
        cudaEventCreateWithFlags(&e_prep, cudaEventDisableTiming);
        cudaEventCreateWithFlags(&e_vert, cudaEventDisableTiming);
        cudaEventCreateWithFlags(&e_gv,   cudaEventDisableTiming);
        cudaFuncSetAttribute(gemm_fp16<2, 0>,
                             cudaFuncAttributeMaxDynamicSharedMemorySize, SMEM_NF2);
        cudaFuncSetAttribute(gemm_fp16<4, 1>,
                             cudaFuncAttributeMaxDynamicSharedMemorySize, SMEM_NF4);
        cudaFuncSetAttribute(gemm_fp16<4, 2>,
                             cudaFuncAttributeMaxDynamicSharedMemorySize, SMEM_NF4);
    }

    __half *p_vh, *p_ph, *p_bv, *p_bp, *p_hh, *p_w2h;
    float *p_P;
    cudaGetSymbolAddress((void**)&p_vh,  g_vh);
    cudaGetSymbolAddress((void**)&p_ph,  g_ph);
    cudaGetSymbolAddress((void**)&p_bv,  g_bv);
    cudaGetSymbolAddress((void**)&p_bp,  g_bp);
    cudaGetSymbolAddress((void**)&p_hh,  g_hh);
    cudaGetSymbolAddress((void**)&p_w2h, g_w2h);
    cudaGetSymbolAddress((void**)&p_P,   g_P);

    // Fork: prep_all runs on s1 concurrently with the span->vertex chain.
    cudaEventRecord(e_root, 0);
    cudaStreamWaitEvent(s1, e_root, 0);
    cudaStreamWaitEvent(s2, e_root, 0);

    prep_all<<<952, 256, 0, s1>>>(W1, W2, dis);
    cudaEventRecord(e_prep, s1);

    span_kernel<<<Bx * NSx, 192, 0, 0>>>(sent, spans);
    vertex_kernel<<<NVERT, 192, 0, 0>>>(vidx, vmask);
    cudaEventRecord(e_vert, 0);

    // GEMM_V on s2 (needs vertex + prep), concurrent with feat_prod on 0.
    cudaStreamWaitEvent(s2, e_vert, 0);
    cudaStreamWaitEvent(s2, e_prep, 0);
    gemm_fp16<2, 0><<<dim3(768 / 32, NVERT / 128), 256, SMEM_NF2, s2>>>(
        p_vh, p_bv, p_P, 768, KD, KD / BKx, nullptr, nullptr, nullptr, nullptr);
    cudaEventRecord(e_gv, s2);

    feat_prod<<<MROWS, 192, 0, 0>>>(hti);

    // Join: GEMM_P on stream 0 needs feat (program order) + prep + GEMM_V.
    cudaStreamWaitEvent(0, e_prep, 0);
    cudaStreamWaitEvent(0, e_gv, 0);
    gemm_fp16<4, 1><<<dim3(HIDx / 64, MROWS / 128), 256, SMEM_NF4, 0>>>(
        p_ph, p_bp, nullptr, HIDx, KD, KD / BKx, hti, dht, dth, nullptr);
    gemm_fp16<4, 2><<<dim3(128 / 64, MROWS / 128), 256, SMEM_NF4, 0>>>(
        p_hh, p_w2h, out, RELx, HIDx, HIDx / BKx, nullptr, nullptr, nullptr, b2);
}

// round 13
// speedup vs baseline: 5.8129x; 1.0324x over previous
#include <cuda_runtime.h>
#include <cuda_fp16.h>
#include <cstdint>

// Problem constants
#define Bx    16
#define Sx    1024
#define Dx    768
#define NSx   256
#define Vx    128
#define Cx    6
#define Rx    512
#define RELx  97
#define HIDx  384
#define DISx  20
#define FINx  (Dx + DISx)          // 788
#define KF    (2 * FINx + Dx)      // 2344
#define MROWS (Bx * Rx)            // 8192
#define NVERT (Bx * Vx)            // 2048
#define KD    768
#define BKx   32

// W1 row-block offsets: [head 0..767 | eh 768..787 | tail 788..1555 |
//                        et 1556..1575 | prod 1576..2343]
#define W1_EH   768
#define W1_TAIL 788
#define W1_ET   1556
#define W1_PROD 1576

// Scratch (static device globals — no allocation allowed)
__device__ float g_span[(size_t)Bx * NSx * Dx];
__device__ float g_vert[(size_t)NVERT * Dx];
__device__ __align__(16) __half g_vh[(size_t)NVERT * KD];    // vertex fp16
__device__ __align__(16) __half g_ph[(size_t)MROWS * KD];    // head*tail fp16
__device__ __align__(16) __half g_bv[(size_t)768 * KD];      // [W1a|W1c]^T
__device__ __align__(16) __half g_bp[(size_t)HIDx * KD];     // W1e^T
__device__ __align__(16) __half g_hh[(size_t)MROWS * HIDx];  // hid fp16
__device__ __align__(16) __half g_w2h[(size_t)128 * HIDx];   // W2^T padded
__device__ float g_P[(size_t)NVERT * 768];                   // vertex proj
__device__ float g_e1[20 * HIDx];
__device__ float g_e2[20 * HIDx];

// ---------------------------------------------------------------------------
// PTX helpers (sm_80-era only — tcgen05 won't assemble for compute_103)
// ---------------------------------------------------------------------------
__device__ __forceinline__ uint32_t smem_u32(const void* p) {
    uint32_t a;
    asm("{ .reg .u64 t; cvta.to.shared.u64 t, %1; cvt.u32.u64 %0, t; }"
        : "=r"(a) : "l"(p));
    return a;
}

__device__ __forceinline__ void ldsm4(uint32_t* r, uint32_t addr) {
    asm volatile("ldmatrix.sync.aligned.m8n8.x4.shared.b16 {%0,%1,%2,%3}, [%4];"
                 : "=r"(r[0]), "=r"(r[1]), "=r"(r[2]), "=r"(r[3]) : "r"(addr));
}

__device__ __forceinline__ void mma_fp16(float* d, const uint32_t* a,
                                         uint32_t b0, uint32_t b1) {
    asm volatile(
        "mma.sync.aligned.m16n8k16.row.col.f32.f16.f16.f32 "
        "{%0,%1,%2,%3}, {%4,%5,%6,%7}, {%8,%9}, {%0,%1,%2,%3};"
        : "+f"(d[0]), "+f"(d[1]), "+f"(d[2]), "+f"(d[3])
        : "r"(a[0]), "r"(a[1]), "r"(a[2]), "r"(a[3]), "r"(b0), "r"(b1));
}

__device__ __forceinline__ void cp16(uint32_t dst, const void* src) {
    asm volatile("cp.async.cg.shared.global [%0], [%1], 16;"
                 :: "r"(dst), "l"(src));
}
#define CP_COMMIT() asm volatile("cp.async.commit_group;" ::: "memory")
#define CP_WAIT(n)  asm volatile("cp.async.wait_group %0;" :: "n"(n) : "memory")

// ---------------------------------------------------------------------------
// Stage 1: span max-pool
// ---------------------------------------------------------------------------
__global__ void span_kernel(const float* __restrict__ sent,
                            const int* __restrict__ spans) {
    int bs = blockIdx.x;
    int b  = bs / NSx;
    int start = spans[bs * 2 + 0];
    int end   = spans[bs * 2 + 1];
    int w = end - start;
    const float4* base = (const float4*)(sent + ((size_t)b * Sx + start) * Dx);
    int t = threadIdx.x;
    float4 m = base[t];
    for (int j = 1; j <= w; j++) {
        float4 v = base[(size_t)j * (Dx / 4) + t];
        m.x = fmaxf(m.x, v.x); m.y = fmaxf(m.y, v.y);
        m.z = fmaxf(m.z, v.z); m.w = fmaxf(m.w, v.w);
    }
    ((float4*)(g_span + (size_t)bs * Dx))[t] = m;
}

// ---------------------------------------------------------------------------
// Stage 2: vertex masked mean (fp32 + fp16 for GEMM_V)
// ---------------------------------------------------------------------------
__global__ void vertex_kernel(const int* __restrict__ vidx,
                              const int* __restrict__ vmask) {
    int bv = blockIdx.x;
    int b  = bv / Vx;
    int t  = threadIdx.x;             // 0..191
    float4 acc = make_float4(0.f, 0.f, 0.f, 0.f);
    float cnt = 0.f;
    #pragma unroll
    for (int c = 0; c < Cx; c++) {
        int mk = vmask[bv * Cx + c];
        if (mk) {
            int idx = vidx[bv * Cx + c];
            float4 v = ((const float4*)(g_span + ((size_t)b * NSx + idx) * Dx))[t];
            acc.x += v.x; acc.y += v.y; acc.z += v.z; acc.w += v.w;
            cnt += 1.f;
        }
    }
    float inv = 1.f / fmaxf(cnt, 1.f);
    acc.x *= inv; acc.y *= inv; acc.z *= inv; acc.w *= inv;
    ((float4*)(g_vert + (size_t)bv * Dx))[t] = acc;

    size_t o2 = (size_t)bv * (KD / 2) + t * 2;
    ((__half2*)g_vh)[o2]     = __floats2half2_rn(acc.x, acc.y);
    ((__half2*)g_vh)[o2 + 1] = __floats2half2_rn(acc.z, acc.w);
}

// ---------------------------------------------------------------------------
// Stage 3: product features  head∘tail -> fp16  (8192 x 768)
// ---------------------------------------------------------------------------
__global__ void feat_prod(const int* __restrict__ hti) {
    int m = blockIdx.x;
    int b = m / Rx;
    int h  = hti[m * 2 + 0];
    int tl = hti[m * 2 + 1];
    const float4* hp = (const float4*)(g_vert + ((size_t)b * Vx + h)  * Dx);
    const float4* tp = (const float4*)(g_vert + ((size_t)b * Vx + tl) * Dx);
    int t = threadIdx.x;              // 0..191
    float4 a = hp[t], c = tp[t];
    size_t o2 = (size_t)m * (KD / 2) + t * 2;
    ((__half2*)g_ph)[o2]     = __floats2half2_rn(a.x * c.x, a.y * c.y);
    ((__half2*)g_ph)[o2 + 1] = __floats2half2_rn(a.z * c.z, a.w * c.w);
}

// ---------------------------------------------------------------------------
// Stage 3b: merged weight prep (coalesced tile transpose) + distance tables.
//   blocks [0,576):    Bv[768 x 768]  = [W1a | W1c]^T
//   blocks [576,864):  Bp[384 x 768]  = W1e^T
//   blocks [864,912):  W2t[128 x 384] = W2^T (padded rows >= 97 are zero)
//   blocks [912,952):  E1/E2[20 x 384] fp32 (exact)
// ---------------------------------------------------------------------------
__global__ void prep_all(const float* __restrict__ W1,
                         const float* __restrict__ W2,
                         const float* __restrict__ dis) {
    __shared__ float tile[32][33];
    int idx = blockIdx.x;
    int t  = threadIdx.x;
    int tx = t & 31, ty = t >> 5;       // 32 x 8

    if (idx < 912) {
        int k0, n0;
        const float* src;
        int src_ld, src_guard;
        __half* dst;
        if (idx < 576) {                // Bv: 24 k-tiles x 24 n-tiles
            int kt = idx / 24, nt = idx % 24;
            k0 = kt * 32; n0 = nt * 32;
            if (n0 < 384) { src = W1 + (size_t)k0 * HIDx + n0; }
            else          { src = W1 + (size_t)(W1_TAIL + k0) * HIDx + (n0 - 384); }
            src_ld = HIDx; src_guard = 32;
            dst = g_bv + (size_t)n0 * KD + k0;
        } else if (idx < 864) {         // Bp: 24 k-tiles x 12 n-tiles
            int q = idx - 576;
            int kt = q / 12, nt = q % 12;
            k0 = kt * 32; n0 = nt * 32;
            src = W1 + (size_t)(W1_PROD + k0) * HIDx + n0;
            src_ld = HIDx; src_guard = 32;
            dst = g_bp + (size_t)n0 * KD + k0;
        } else {                        // W2t: 12 k-tiles x 4 n-tiles
            int q = idx - 864;
            int kt = q / 4, nt = q % 4;
            k0 = kt * 32; n0 = nt * 32;
            src = W2 + (size_t)k0 * RELx + n0;
            src_ld = RELx;
            src_guard = (n0 + 32 <= RELx) ? 32 : (RELx > n0 ? RELx - n0 : 0);
            dst = g_w2h + (size_t)n0 * HIDx + k0;
        }
        #pragma unroll
        for (int i = 0; i < 4; i++) {
            int r = i * 8 + ty;
            tile[r][tx] = (tx < src_guard) ? src[(size_t)r * src_ld + tx] : 0.f;
        }
        __syncthreads();
        int KOUT = (idx < 864) ? KD : HIDx;
        #pragma unroll
        for (int i = 0; i < 4; i++) {
            int r = i * 8 + ty;         // n within tile
            dst[(size_t)r * KOUT + tx] = __float2half(tile[tx][r]);
        }
    } else {                            // distance tables
        int q = idx - 912;
        int d = q % 20, which = q / 20;
        int wbase = which ? W1_ET : W1_EH;
        float* outp = which ? g_e2 : g_e1;
        for (int n = t; n < HIDx; n += 256) {
            float s = 0.f;
            #pragma unroll
            for (int j = 0; j < DISx; j++)
                s += dis[d * DISx + j] * W1[(size_t)(wbase + j) * HIDx + n];
            outp[d * HIDx + n] = s;
        }
    }
}

// ---------------------------------------------------------------------------
// Single-stream fp16 HMMA GEMM: out[M x N] = A[M x K] * B[N x K]^T, fp32 accum
//   BM=128, BN=NF*16; 8 warps (4m x 2n); 3 CTAs/SM.
//   4-stage cp.async pipeline (3 chunks in flight, CP_WAIT(2)); barrier at
//   loop top; uniform one-commit-per-iter (empty commits keep group numbering
//   aligned so the constant wait is always correct, incl. tail).
//   MODE 0: plain fp32 store (GEMM_V -> P)
//   MODE 1: + gathered P/E1/E2 terms, ReLU, fp16 store (GEMM_P -> hid)
//   MODE 2: + bias, n<RELx guard, fp32 store (GEMM2 -> out)
// ---------------------------------------------------------------------------
#define PAD 40                          // fp16 elems per smem row (80B stride)
#define NSTG 4                          // pipeline stages

template <int NF, int MODE>
__global__ __launch_bounds__(256, 3) void gemm_fp16(
    const __half* __restrict__ A, const __half* __restrict__ B,
    float* __restrict__ out, int ldc, int K, int nch,
    const int* __restrict__ hti, const int* __restrict__ dht,
    const int* __restrict__ dth, const float* __restrict__ bias) {
    constexpr int BN    = NF * 16;
    constexpr int ARR_A = 128 * PAD * 2;
    constexpr int ARR_B = BN * PAD * 2;
    constexpr int STG   = ARR_A + ARR_B;

    extern __shared__ char smem[];
    uint32_t sb = smem_u32(smem);
    int t = threadIdx.x, wid = t >> 5, lane = t & 31;
    int n0 = blockIdx.x * BN;
    int m0 = blockIdx.y * 128;
    int wm = (wid & 3) * 32;
    int wn = (wid >> 2) * (NF * 8);

    float acc[2][NF][4];
    #pragma unroll
    for (int i = 0; i < 2; i++)
        #pragma unroll
        for (int j = 0; j < NF; j++)
            #pragma unroll
            for (int q = 0; q < 4; q++) acc[i][j][q] = 0.f;

    auto load_chunk = [&](int k0, int s) {
        uint32_t stg = sb + (uint32_t)s * STG;
        #pragma unroll
        for (int i = 0; i < 2; i++) {               // A: 512 16B chunks
            int e = (i << 8) + t;
            int r = e >> 2;
            int c = e & 3;
            cp16(stg + r * (PAD * 2) + c * 16,
                 A + (size_t)(m0 + r) * K + k0 + c * 8);
        }
        if (t < BN * 4) {                           // B: BN*4 chunks
            int r = t >> 2, c = t & 3;
            cp16(stg + ARR_A + r * (PAD * 2) + c * 16,
                 B + (size_t)(n0 + r) * K + k0 + c * 8);
        }
    };

    // Prologue: chunks 0..NSTG-2, one commit each.
    #pragma unroll
    for (int i = 0; i < NSTG - 1; i++) {
        if (i < nch) load_chunk(i * BKx, i);
        CP_COMMIT();
    }

    int lr = lane & 15;
    int lc = lane >> 4;

    for (int c = 0; c < nch; c++) {
        CP_WAIT(NSTG - 2);              // chunk c resident
        __syncthreads();                // stage (c-1)%NSTG now reusable

        int pf = c + NSTG - 1;
        if (pf < nch) load_chunk(pf * BKx, pf & (NSTG - 1));
        CP_COMMIT();                    // real or empty — keeps numbering

        uint32_t a_base = sb + (uint32_t)(c & (NSTG - 1)) * STG;
        uint32_t b_base = a_base + ARR_A;

        #pragma unroll
        for (int ks = 0; ks < 2; ks++) {
            uint32_t koff = (uint32_t)(ks * 16 + lc * 8) * 2;
            uint32_t af[2][4];
            #pragma unroll
            for (int mf = 0; mf < 2; mf++) {
                uint32_t ro = (uint32_t)(wm + mf * 16 + lr) * (PAD * 2) + koff;
                ldsm4(af[mf], a_base + ro);
            }
            uint32_t bf[NF * 2];
            #pragma unroll
            for (int g = 0; g < NF / 2; g++) {
                uint32_t ro = (uint32_t)(wn + g * 16 + lr) * (PAD * 2) + koff;
                ldsm4(&bf[g * 4], b_base + ro);
            }
            #pragma unroll
            for (int mf = 0; mf < 2; mf++) {
                #pragma unroll
                for (int nf = 0; nf < NF; nf++) {
                    int bi = (nf >> 1) * 4 + (nf & 1);
                    mma_fp16(acc[mf][nf], af[mf], bf[bi], bf[bi + 2]);
                }
            }
        }
    }

    int row  = lane >> 2;
    int colp = (lane & 3) * 2;
    if (MODE == 0) {
        #pragma unroll
        for (int mf = 0; mf < 2; mf++) {
            #pragma unroll
            for (int nf = 0; nf < NF; nf++) {
                int r0 = m0 + wm + mf * 16 + row;
                int cc = n0 + wn + nf * 8 + colp;
                *(float2*)(out + (size_t)r0 * ldc + cc) =
                    make_float2(acc[mf][nf][0], acc[mf][nf][1]);
                *(float2*)(out + (size_t)(r0 + 8) * ldc + cc) =
                    make_float2(acc[mf][nf][2], acc[mf][nf][3]);
            }
        }
    } else if (MODE == 1) {
        // + P[h] + P[t] + E1 + E2, ReLU, fp16 -> g_hh
        #pragma unroll
        for (int mf = 0; mf < 2; mf++) {
            #pragma unroll
            for (int rr = 0; rr < 2; rr++) {
                int r = m0 + wm + mf * 16 + row + rr * 8;
                int b = r / Rx;
                int hrow = b * Vx + hti[r * 2 + 0];
                int trow = b * Vx + hti[r * 2 + 1];
                const float* ph = g_P + (size_t)hrow * 768;
                const float* pt = g_P + (size_t)trow * 768 + HIDx;
                const float* e1 = g_e1 + dht[r] * HIDx;
                const float* e2 = g_e2 + dth[r] * HIDx;
                #pragma unroll
                for (int nf = 0; nf < NF; nf++) {
                    int cc = n0 + wn + nf * 8 + colp;
                    float2 a0 = *(const float2*)(ph + cc);
                    float2 a1 = *(const float2*)(pt + cc);
                    float2 a2 = *(const float2*)(e1 + cc);
                    float2 a3 = *(const float2*)(e2 + cc);
                    float v0 = fmaxf(acc[mf][nf][rr * 2 + 0] + a0.x + a1.x + a2.x + a3.x, 0.f);
                    float v1 = fmaxf(acc[mf][nf][rr * 2 + 1] + a0.y + a1.y + a2.y + a3.y, 0.f);
                    ((__half2*)g_hh)[((size_t)r * HIDx + cc) / 2] =
                        __floats2half2_rn(v0, v1);
                }
            }
        }
    } else {
        // + bias, guard n < RELx, fp32 -> out
        #pragma unroll
        for (int mf = 0; mf < 2; mf++) {
            #pragma unroll
            for (int rr = 0; rr < 2; rr++) {
                int r = m0 + wm + mf * 16 + row + rr * 8;
                #pragma unroll
                for (int nf = 0; nf < NF; nf++) {
                    int cc = n0 + wn + nf * 8 + colp;
                    if (cc < RELx)
                        out[(size_t)r * RELx + cc] =
                            acc[mf][nf][rr * 2 + 0] + bias[cc];
                    if (cc + 1 < RELx)
                        out[(size_t)r * RELx + cc + 1] =
                            acc[mf][nf][rr * 2 + 1] + bias[cc + 1];
                }
            }
        }
    }
}

#define SMEM_NF4 (NSTG * (128 * PAD * 2 + 64 * PAD * 2))   // 61440
#define SMEM_NF2 (NSTG * (128 * PAD * 2 + 32 * PAD * 2))   // 51200

// ---------------------------------------------------------------------------
// Launch — fork/join stream DAG (captured as a branching CUDA graph):
//   stream0: span -> vertex -> feat ----------\
//   s1:      prep_all (independent) --- e_prep +--> GEMM_P -> GEMM2
//   s2:      [vertex, prep] -> GEMM_V --- e_gv /
// ---------------------------------------------------------------------------
extern "C" void kernel_launch(void* const* d_in, const int* in_sizes, int n_in,
                              void* d_out, int out_size) {
    const float* sent  = (const float*)d_in[0];
    const int*   spans = (const int*)d_in[1];
    const int*   vidx  = (const int*)d_in[3];
    const int*   vmask = (const int*)d_in[4];
    const int*   hti   = (const int*)d_in[5];
    const int*   dht   = (const int*)d_in[7];
    const int*   dth   = (const int*)d_in[8];
    const float* dis   = (const float*)d_in[9];
    const float* W1    = (const float*)d_in[10];
    const float* W2    = (const float*)d_in[11];
    const float* b2    = (const float*)d_in[12];
    float* out = (float*)d_out;

    static cudaStream_t s1 = nullptr, s2 = nullptr;
    static cudaEvent_t e_root = nullptr, e_prep = nullptr, e_vert = nullptr,
                       e_gv = nullptr;
    if (!s1) {
        cudaStreamCreateWithFlags(&s1, cudaStreamNonBlocking);
        cudaStreamCreateWithFlags(&s2, cudaStreamNonBlocking);
        cudaEventCreateWithFlags(&e_root, cudaEventDisableTiming);
        cudaEventCreateWithFlags(&e_prep, cudaEventDisableTiming);
        cudaEventCreateWithFlags(&e_vert, cudaEventDisableTiming);
        cudaEventCreateWithFlags(&e_gv,   cudaEventDisableTiming);
        cudaFuncSetAttribute(gemm_fp16<2, 0>,
                             cudaFuncAttributeMaxDynamicSharedMemorySize, SMEM_NF2);
        cudaFuncSetAttribute(gemm_fp16<4, 1>,
                             cudaFuncAttributeMaxDynamicSharedMemorySize, SMEM_NF4);
        cudaFuncSetAttribute(gemm_fp16<4, 2>,
                             cudaFuncAttributeMaxDynamicSharedMemorySize, SMEM_NF4);
    }

    __half *p_vh, *p_ph, *p_bv, *p_bp, *p_hh, *p_w2h;
    float *p_P;
    cudaGetSymbolAddress((void**)&p_vh,  g_vh);
    cudaGetSymbolAddress((void**)&p_ph,  g_ph);
    cudaGetSymbolAddress((void**)&p_bv,  g_bv);
    cudaGetSymbolAddress((void**)&p_bp,  g_bp);
    cudaGetSymbolAddress((void**)&p_hh,  g_hh);
    cudaGetSymbolAddress((void**)&p_w2h, g_w2h);
    cudaGetSymbolAddress((void**)&p_P,   g_P);

    // Fork: prep_all runs on s1 concurrently with the span->vertex chain.
    cudaEventRecord(e_root, 0);
    cudaStreamWaitEvent(s1, e_root, 0);
    cudaStreamWaitEvent(s2, e_root, 0);

    prep_all<<<952, 256, 0, s1>>>(W1, W2, dis);
    cudaEventRecord(e_prep, s1);

    span_kernel<<<Bx * NSx, 192, 0, 0>>>(sent, spans);
    vertex_kernel<<<NVERT, 192, 0, 0>>>(vidx, vmask);
    cudaEventRecord(e_vert, 0);

    // GEMM_V on s2 (needs vertex + prep), concurrent with feat_prod on 0.
    cudaStreamWaitEvent(s2, e_vert, 0);
    cudaStreamWaitEvent(s2, e_prep, 0);
    gemm_fp16<2, 0><<<dim3(768 / 32, NVERT / 128), 256, SMEM_NF2, s2>>>(
        p_vh, p_bv, p_P, 768, KD, KD / BKx, nullptr, nullptr, nullptr, nullptr);
    cudaEventRecord(e_gv, s2);

    feat_prod<<<MROWS, 192, 0, 0>>>(hti);

    // Join: GEMM_P on stream 0 needs feat (program order) + prep + GEMM_V.
    cudaStreamWaitEvent(0, e_prep, 0);
    cudaStreamWaitEvent(0, e_gv, 0);
    gemm_fp16<4, 1><<<dim3(HIDx / 64, MROWS / 128), 256, SMEM_NF4, 0>>>(
        p_ph, p_bp, nullptr, HIDx, KD, KD / BKx, hti, dht, dth, nullptr);
    gemm_fp16<4, 2><<<dim3(128 / 64, MROWS / 128), 256, SMEM_NF4, 0>>>(
        p_hh, p_w2h, out, RELx, HIDx, HIDx / BKx, nullptr, nullptr, nullptr, b2);
}

// round 14
// speedup vs baseline: 5.9479x; 1.0232x over previous
#include <cuda_runtime.h>
#include <cuda_fp16.h>
#include <cstdint>

// Problem constants
#define Bx    16
#define Sx    1024
#define Dx    768
#define NSx   256
#define Vx    128
#define Cx    6
#define Rx    512
#define RELx  97
#define HIDx  384
#define DISx  20
#define FINx  (Dx + DISx)          // 788
#define KF    (2 * FINx + Dx)      // 2344
#define MROWS (Bx * Rx)            // 8192
#define NVERT (Bx * Vx)            // 2048
#define KD    768
#define BKx   32

// W1 row-block offsets
#define W1_EH   768
#define W1_TAIL 788
#define W1_ET   1556
#define W1_PROD 1576

// Scratch (static device globals — no allocation allowed)
__device__ float g_span[(size_t)Bx * NSx * Dx];
__device__ float g_vert[(size_t)NVERT * Dx];
__device__ __align__(16) __half g_vh[(size_t)NVERT * KD];    // vertex fp16
__device__ __align__(16) __half g_ph[(size_t)MROWS * KD];    // head*tail fp16
__device__ __align__(16) __half g_bv[(size_t)768 * KD];      // [W1a|W1c]^T
__device__ __align__(16) __half g_bp[(size_t)HIDx * KD];     // W1e^T
__device__ __align__(16) __half g_hh[(size_t)MROWS * HIDx];  // hid fp16
__device__ __align__(16) __half g_w2h[(size_t)128 * HIDx];   // W2^T padded
__device__ float g_P[(size_t)NVERT * 768];                   // vertex proj
__device__ float g_acc[(size_t)MROWS * HIDx];                // GEMM_P raw acc
__device__ float g_e1[20 * HIDx];
__device__ float g_e2[20 * HIDx];

// ---------------------------------------------------------------------------
// PTX helpers (sm_80-era only — tcgen05 won't assemble for compute_103)
// ---------------------------------------------------------------------------
__device__ __forceinline__ uint32_t smem_u32(const void* p) {
    uint32_t a;
    asm("{ .reg .u64 t; cvta.to.shared.u64 t, %1; cvt.u32.u64 %0, t; }"
        : "=r"(a) : "l"(p));
    return a;
}

__device__ __forceinline__ void ldsm4(uint32_t* r, uint32_t addr) {
    asm volatile("ldmatrix.sync.aligned.m8n8.x4.shared.b16 {%0,%1,%2,%3}, [%4];"
                 : "=r"(r[0]), "=r"(r[1]), "=r"(r[2]), "=r"(r[3]) : "r"(addr));
}

__device__ __forceinline__ void mma_fp16(float* d, const uint32_t* a,
                                         uint32_t b0, uint32_t b1) {
    asm volatile(
        "mma.sync.aligned.m16n8k16.row.col.f32.f16.f16.f32 "
        "{%0,%1,%2,%3}, {%4,%5,%6,%7}, {%8,%9}, {%0,%1,%2,%3};"
        : "+f"(d[0]), "+f"(d[1]), "+f"(d[2]), "+f"(d[3])
        : "r"(a[0]), "r"(a[1]), "r"(a[2]), "r"(a[3]), "r"(b0), "r"(b1));
}

__device__ __forceinline__ void cp16(uint32_t dst, const void* src) {
    asm volatile("cp.async.cg.shared.global [%0], [%1], 16;"
                 :: "r"(dst), "l"(src));
}
#define CP_COMMIT() asm volatile("cp.async.commit_group;" ::: "memory")
#define CP_WAIT(n)  asm volatile("cp.async.wait_group %0;" :: "n"(n) : "memory")

// ---------------------------------------------------------------------------
// Stage 1: span max-pool
// ---------------------------------------------------------------------------
__global__ void span_kernel(const float* __restrict__ sent,
                            const int* __restrict__ spans) {
    int bs = blockIdx.x;
    int b  = bs / NSx;
    int start = spans[bs * 2 + 0];
    int end   = spans[bs * 2 + 1];
    int w = end - start;
    const float4* base = (const float4*)(sent + ((size_t)b * Sx + start) * Dx);
    int t = threadIdx.x;
    float4 m = base[t];
    for (int j = 1; j <= w; j++) {
        float4 v = base[(size_t)j * (Dx / 4) + t];
        m.x = fmaxf(m.x, v.x); m.y = fmaxf(m.y, v.y);
        m.z = fmaxf(m.z, v.z); m.w = fmaxf(m.w, v.w);
    }
    ((float4*)(g_span + (size_t)bs * Dx))[t] = m;
}

// ---------------------------------------------------------------------------
// Stage 2: vertex masked mean (fp32 + fp16 for GEMM_V)
// ---------------------------------------------------------------------------
__global__ void vertex_kernel(const int* __restrict__ vidx,
                              const int* __restrict__ vmask) {
    int bv = blockIdx.x;
    int b  = bv / Vx;
    int t  = threadIdx.x;             // 0..191
    float4 acc = make_float4(0.f, 0.f, 0.f, 0.f);
    float cnt = 0.f;
    #pragma unroll
    for (int c = 0; c < Cx; c++) {
        int mk = vmask[bv * Cx + c];
        if (mk) {
            int idx = vidx[bv * Cx + c];
            float4 v = ((const float4*)(g_span + ((size_t)b * NSx + idx) * Dx))[t];
            acc.x += v.x; acc.y += v.y; acc.z += v.z; acc.w += v.w;
            cnt += 1.f;
        }
    }
    float inv = 1.f / fmaxf(cnt, 1.f);
    acc.x *= inv; acc.y *= inv; acc.z *= inv; acc.w *= inv;
    ((float4*)(g_vert + (size_t)bv * Dx))[t] = acc;

    size_t o2 = (size_t)bv * (KD / 2) + t * 2;
    ((__half2*)g_vh)[o2]     = __floats2half2_rn(acc.x, acc.y);
    ((__half2*)g_vh)[o2 + 1] = __floats2half2_rn(acc.z, acc.w);
}

// ---------------------------------------------------------------------------
// Stage 3: product features  head∘tail -> fp16  (8192 x 768)
// ---------------------------------------------------------------------------
__global__ void feat_prod(const int* __restrict__ hti) {
    int m = blockIdx.x;
    int b = m / Rx;
    int h  = hti[m * 2 + 0];
    int tl = hti[m * 2 + 1];
    const float4* hp = (const float4*)(g_vert + ((size_t)b * Vx + h)  * Dx);
    const float4* tp = (const float4*)(g_vert + ((size_t)b * Vx + tl) * Dx);
    int t = threadIdx.x;              // 0..191
    float4 a = hp[t], c = tp[t];
    size_t o2 = (size_t)m * (KD / 2) + t * 2;
    ((__half2*)g_ph)[o2]     = __floats2half2_rn(a.x * c.x, a.y * c.y);
    ((__half2*)g_ph)[o2 + 1] = __floats2half2_rn(a.z * c.z, a.w * c.w);
}

// ---------------------------------------------------------------------------
// Stage 3b: merged weight prep (coalesced tile transpose) + distance tables.
// ---------------------------------------------------------------------------
__global__ void prep_all(const float* __restrict__ W1,
                         const float* __restrict__ W2,
                         const float* __restrict__ dis) {
    __shared__ float tile[32][33];
    int idx = blockIdx.x;
    int t  = threadIdx.x;
    int tx = t & 31, ty = t >> 5;       // 32 x 8

    if (idx < 912) {
        int k0, n0;
        const float* src;
        int src_ld, src_guard;
        __half* dst;
        if (idx < 576) {                // Bv: 24 k-tiles x 24 n-tiles
            int kt = idx / 24, nt = idx % 24;
            k0 = kt * 32; n0 = nt * 32;
            if (n0 < 384) { src = W1 + (size_t)k0 * HIDx + n0; }
            else          { src = W1 + (size_t)(W1_TAIL + k0) * HIDx + (n0 - 384); }
            src_ld = HIDx; src_guard = 32;
            dst = g_bv + (size_t)n0 * KD + k0;
        } else if (idx < 864) {         // Bp: 24 k-tiles x 12 n-tiles
            int q = idx - 576;
            int kt = q / 12, nt = q % 12;
            k0 = kt * 32; n0 = nt * 32;
            src = W1 + (size_t)(W1_PROD + k0) * HIDx + n0;
            src_ld = HIDx; src_guard = 32;
            dst = g_bp + (size_t)n0 * KD + k0;
        } else {                        // W2t: 12 k-tiles x 4 n-tiles
            int q = idx - 864;
            int kt = q / 4, nt = q % 4;
            k0 = kt * 32; n0 = nt * 32;
            src = W2 + (size_t)k0 * RELx + n0;
            src_ld = RELx;
            src_guard = (n0 + 32 <= RELx) ? 32 : (RELx > n0 ? RELx - n0 : 0);
            dst = g_w2h + (size_t)n0 * HIDx + k0;
        }
        #pragma unroll
        for (int i = 0; i < 4; i++) {
            int r = i * 8 + ty;
            tile[r][tx] = (tx < src_guard) ? src[(size_t)r * src_ld + tx] : 0.f;
        }
        __syncthreads();
        int KOUT = (idx < 864) ? KD : HIDx;
        #pragma unroll
        for (int i = 0; i < 4; i++) {
            int r = i * 8 + ty;         // n within tile
            dst[(size_t)r * KOUT + tx] = __float2half(tile[tx][r]);
        }
    } else {                            // distance tables
        int q = idx - 912;
        int d = q % 20, which = q / 20;
        int wbase = which ? W1_ET : W1_EH;
        float* outp = which ? g_e2 : g_e1;
        for (int n = t; n < HIDx; n += 256) {
            float s = 0.f;
            #pragma unroll
            for (int j = 0; j < DISx; j++)
                s += dis[d * DISx + j] * W1[(size_t)(wbase + j) * HIDx + n];
            outp[d * HIDx + n] = s;
        }
    }
}

// ---------------------------------------------------------------------------
// hid epilogue: hid = relu(acc + P[h] + P[t] + E1 + E2) -> fp16
// Same add order as before (acc + ph + pt + e1 + e2) => bit-identical.
// grid 8192, 192 threads (float2 over 384 cols).
// ---------------------------------------------------------------------------
__global__ void hid_epi(const int* __restrict__ hti,
                        const int* __restrict__ dht,
                        const int* __restrict__ dth) {
    int r = blockIdx.x;
    int b = r / Rx;
    int hrow = b * Vx + hti[r * 2 + 0];
    int trow = b * Vx + hti[r * 2 + 1];
    const float2* ac = (const float2*)(g_acc + (size_t)r * HIDx);
    const float2* ph = (const float2*)(g_P + (size_t)hrow * 768);
    const float2* pt = (const float2*)(g_P + (size_t)trow * 768 + HIDx);
    const float2* e1 = (const float2*)(g_e1 + dht[r] * HIDx);
    const float2* e2 = (const float2*)(g_e2 + dth[r] * HIDx);
    int t = threadIdx.x;              // 0..191
    float2 a  = ac[t];
    float2 p0 = ph[t], p1 = pt[t], q0 = e1[t], q1 = e2[t];
    float v0 = fmaxf(a.x + p0.x + p1.x + q0.x + q1.x, 0.f);
    float v1 = fmaxf(a.y + p0.y + p1.y + q0.y + q1.y, 0.f);
    ((__half2*)g_hh)[(size_t)r * (HIDx / 2) + t] = __floats2half2_rn(v0, v1);
}

// ---------------------------------------------------------------------------
// Single-stream fp16 HMMA GEMM: out[M x N] = A[M x K] * B[N x K]^T, fp32 accum
//   BM=128, BN=NF*16; 8 warps (4m x 2n); OCC CTAs/SM (template).
//   4-stage cp.async pipeline (3 in flight); uniform commit numbering.
//   MODE 0: plain fp32 store
//   MODE 2: + bias, n<RELx guard, fp32 store (GEMM2 -> out)
// ---------------------------------------------------------------------------
#define PAD 40                          // fp16 elems per smem row (80B stride)
#define NSTG 4                          // pipeline stages

template <int NF, int MODE, int OCC>
__global__ __launch_bounds__(256, OCC) void gemm_fp16(
    const __half* __restrict__ A, const __half* __restrict__ B,
    float* __restrict__ out, int ldc, int K, int nch,
    const float* __restrict__ bias) {
    constexpr int BN    = NF * 16;
    constexpr int ARR_A = 128 * PAD * 2;
    constexpr int ARR_B = BN * PAD * 2;
    constexpr int STG   = ARR_A + ARR_B;

    extern __shared__ char smem[];
    uint32_t sb = smem_u32(smem);
    int t = threadIdx.x, wid = t >> 5, lane = t & 31;
    int n0 = blockIdx.x * BN;
    int m0 = blockIdx.y * 128;
    int wm = (wid & 3) * 32;
    int wn = (wid >> 2) * (NF * 8);

    float acc[2][NF][4];
    #pragma unroll
    for (int i = 0; i < 2; i++)
        #pragma unroll
        for (int j = 0; j < NF; j++)
            #pragma unroll
            for (int q = 0; q < 4; q++) acc[i][j][q] = 0.f;

    auto load_chunk = [&](int k0, int s) {
        uint32_t stg = sb + (uint32_t)s * STG;
        #pragma unroll
        for (int i = 0; i < 2; i++) {               // A: 512 16B chunks
            int e = (i << 8) + t;
            int r = e >> 2;
            int c = e & 3;
            cp16(stg + r * (PAD * 2) + c * 16,
                 A + (size_t)(m0 + r) * K + k0 + c * 8);
        }
        if (t < BN * 4) {                           // B: BN*4 chunks
            int r = t >> 2, c = t & 3;
            cp16(stg + ARR_A + r * (PAD * 2) + c * 16,
                 B + (size_t)(n0 + r) * K + k0 + c * 8);
        }
    };

    #pragma unroll
    for (int i = 0; i < NSTG - 1; i++) {
        if (i < nch) load_chunk(i * BKx, i);
        CP_COMMIT();
    }

    int lr = lane & 15;
    int lc = lane >> 4;

    for (int c = 0; c < nch; c++) {
        CP_WAIT(NSTG - 2);
        __syncthreads();

        int pf = c + NSTG - 1;
        if (pf < nch) load_chunk(pf * BKx, pf & (NSTG - 1));
        CP_COMMIT();

        uint32_t a_base = sb + (uint32_t)(c & (NSTG - 1)) * STG;
        uint32_t b_base = a_base + ARR_A;

        #pragma unroll
        for (int ks = 0; ks < 2; ks++) {
            uint32_t koff = (uint32_t)(ks * 16 + lc * 8) * 2;
            uint32_t af[2][4];
            #pragma unroll
            for (int mf = 0; mf < 2; mf++) {
                uint32_t ro = (uint32_t)(wm + mf * 16 + lr) * (PAD * 2) + koff;
                ldsm4(af[mf], a_base + ro);
            }
            uint32_t bf[NF * 2];
            #pragma unroll
            for (int g = 0; g < NF / 2; g++) {
                uint32_t ro = (uint32_t)(wn + g * 16 + lr) * (PAD * 2) + koff;
                ldsm4(&bf[g * 4], b_base + ro);
            }
            #pragma unroll
            for (int mf = 0; mf < 2; mf++) {
                #pragma unroll
                for (int nf = 0; nf < NF; nf++) {
                    int bi = (nf >> 1) * 4 + (nf & 1);
                    mma_fp16(acc[mf][nf], af[mf], bf[bi], bf[bi + 2]);
                }
            }
        }
    }

    int row  = lane >> 2;
    int colp = (lane & 3) * 2;
    if (MODE == 0) {
        #pragma unroll
        for (int mf = 0; mf < 2; mf++) {
            #pragma unroll
            for (int nf = 0; nf < NF; nf++) {
                int r0 = m0 + wm + mf * 16 + row;
                int cc = n0 + wn + nf * 8 + colp;
                *(float2*)(out + (size_t)r0 * ldc + cc) =
                    make_float2(acc[mf][nf][0], acc[mf][nf][1]);
                *(float2*)(out + (size_t)(r0 + 8) * ldc + cc) =
                    make_float2(acc[mf][nf][2], acc[mf][nf][3]);
            }
        }
    } else {
        // + bias, guard n < RELx, fp32 -> out
        #pragma unroll
        for (int mf = 0; mf < 2; mf++) {
            #pragma unroll
            for (int rr = 0; rr < 2; rr++) {
                int r = m0 + wm + mf * 16 + row + rr * 8;
                #pragma unroll
                for (int nf = 0; nf < NF; nf++) {
                    int cc = n0 + wn + nf * 8 + colp;
                    if (cc < RELx)
                        out[(size_t)r * RELx + cc] =
                            acc[mf][nf][rr * 2 + 0] + bias[cc];
                    if (cc + 1 < RELx)
                        out[(size_t)r * RELx + cc + 1] =
                            acc[mf][nf][rr * 2 + 1] + bias[cc + 1];
                }
            }
        }
    }
}

#define SMEM_NF4 (NSTG * (128 * PAD * 2 + 64 * PAD * 2))   // 61440
#define SMEM_NF2 (NSTG * (128 * PAD * 2 + 32 * PAD * 2))   // 51200

// ---------------------------------------------------------------------------
// Launch — fork/join stream DAG:
//   s1: prep_all ------------------------- e_prep
//   0 : span -> vertex -(e_vert)-> feat -> [w e_prep] GEMM_P_main
//   s2: [e_vert, e_prep] GEMM_V ---------- e_gv
//   0 : [w e_gv] hid_epi -> GEMM2
// GEMM_V co-runs with feat + GEMM_P mainloop (false dep broken via g_acc).
// ---------------------------------------------------------------------------
extern "C" void kernel_launch(void* const* d_in, const int* in_sizes, int n_in,
                              void* d_out, int out_size) {
    const float* sent  = (const float*)d_in[0];
    const int*   spans = (const int*)d_in[1];
    const int*   vidx  = (const int*)d_in[3];
    const int*   vmask = (const int*)d_in[4];
    const int*   hti   = (const int*)d_in[5];
    const int*   dht   = (const int*)d_in[7];
    const int*   dth   = (const int*)d_in[8];
    const float* dis   = (const float*)d_in[9];
    const float* W1    = (const float*)d_in[10];
    const float* W2    = (const float*)d_in[11];
    const float* b2    = (const float*)d_in[12];
    float* out = (float*)d_out;

    static cudaStream_t s1 = nullptr, s2 = nullptr;
    static cudaEvent_t e_root = nullptr, e_prep = nullptr, e_vert = nullptr,
                       e_gv = nullptr;
    if (!s1) {
        cudaStreamCreateWithFlags(&s1, cudaStreamNonBlocking);
        cudaStreamCreateWithFlags(&s2, cudaStreamNonBlocking);
        cudaEventCreateWithFlags(&e_root, cudaEventDisableTiming);
        cudaEventCreateWithFlags(&e_prep, cudaEventDisableTiming);
        cudaEventCreateWithFlags(&e_vert, cudaEventDisableTiming);
        cudaEventCreateWithFlags(&e_gv,   cudaEventDisableTiming);
        cudaFuncSetAttribute((const void*)gemm_fp16<2, 0, 4>,
                             cudaFuncAttributeMaxDynamicSharedMemorySize, SMEM_NF2);
        cudaFuncSetAttribute((const void*)gemm_fp16<4, 0, 3>,
                             cudaFuncAttributeMaxDynamicSharedMemorySize, SMEM_NF4);
        cudaFuncSetAttribute((const void*)gemm_fp16<4, 2, 3>,
                             cudaFuncAttributeMaxDynamicSharedMemorySize, SMEM_NF4);
    }

    __half *p_vh, *p_ph, *p_bv, *p_bp, *p_hh, *p_w2h;
    float *p_P, *p_acc;
    cudaGetSymbolAddress((void**)&p_vh,  g_vh);
    cudaGetSymbolAddress((void**)&p_ph,  g_ph);
    cudaGetSymbolAddress((void**)&p_bv,  g_bv);
    cudaGetSymbolAddress((void**)&p_bp,  g_bp);
    cudaGetSymbolAddress((void**)&p_hh,  g_hh);
    cudaGetSymbolAddress((void**)&p_w2h, g_w2h);
    cudaGetSymbolAddress((void**)&p_P,   g_P);
    cudaGetSymbolAddress((void**)&p_acc, g_acc);

    // Fork: prep_all on s1 concurrently with the span->vertex chain.
    cudaEventRecord(e_root, 0);
    cudaStreamWaitEvent(s1, e_root, 0);
    cudaStreamWaitEvent(s2, e_root, 0);

    prep_all<<<952, 256, 0, s1>>>(W1, W2, dis);
    cudaEventRecord(e_prep, s1);

    span_kernel<<<Bx * NSx, 192, 0, 0>>>(sent, spans);
    vertex_kernel<<<NVERT, 192, 0, 0>>>(vidx, vmask);
    cudaEventRecord(e_vert, 0);

    // GEMM_V on s2 (needs vertex + prep), 4 CTAs/SM.
    cudaStreamWaitEvent(s2, e_vert, 0);
    cudaStreamWaitEvent(s2, e_prep, 0);
    gemm_fp16<2, 0, 4><<<dim3(768 / 32, NVERT / 128), 256, SMEM_NF2, s2>>>(
        p_vh, p_bv, p_P, 768, KD, KD / BKx, nullptr);
    cudaEventRecord(e_gv, s2);

    // stream 0: feat, then GEMM_P mainloop (needs only feat + prep — co-runs
    // with GEMM_V on s2).
    feat_prod<<<MROWS, 192, 0, 0>>>(hti);
    cudaStreamWaitEvent(0, e_prep, 0);
    gemm_fp16<4, 0, 3><<<dim3(HIDx / 64, MROWS / 128), 256, SMEM_NF4, 0>>>(
        p_ph, p_bp, p_acc, HIDx, KD, KD / BKx, nullptr);

    // Join: epilogue needs acc + P; then GEMM2.
    cudaStreamWaitEvent(0, e_gv, 0);
    hid_epi<<<MROWS, 192, 0, 0>>>(hti, dht, dth);
    gemm_fp16<4, 2, 3><<<dim3(128 / 64, MROWS / 128), 256, SMEM_NF4, 0>>>(
        p_hh, p_w2h, out, RELx, HIDx, HIDx / BKx, b2);
}